// round 15
// baseline (speedup 1.0000x reference)
#include <cuda_runtime.h>
#include <cuda_bf16.h>
#include <cstdint>
#include <cstddef>

// Problem constants
#define BB   4
#define TT   2048
#define DM   1024
#define DI   2048
#define DX   4096
#define MROWS (BB*TT)   // 8192

// GEMM tiling (128x128 CTA, 16 warps of 32x32)
#define BKC   32
#define PITCH 40
#define TILE_BYTES (128*PITCH*2)
#define STAGE_BYTES (4*TILE_BYTES)
#define NSTAGE 4
#define GEMM_SMEM (NSTAGE*STAGE_BYTES + 1024)
#define GT    512

// Block-scan config
#define RB    64
#define NBLK  32
#define TOTBLK 128
#define PTCH  68
#define SMEMA ((RB*65 + 2*RB*PTCH + RB)*4)

// ---------------- scratch ----------------------------------------------------
__device__ __nv_bfloat16 g_xh [(size_t)MROWS * DM],  g_xl [(size_t)MROWS * DM];
__device__ __nv_bfloat16 g_winh[(size_t)DX * DM],    g_winl[(size_t)DX * DM];
__device__ __nv_bfloat16 g_wlh[(size_t)DI * DI],     g_wll[(size_t)DI * DI];
__device__ __nv_bfloat16 g_wvh[(size_t)DI * DI],     g_wvl[(size_t)DI * DI];
__device__ __nv_bfloat16 g_woh[(size_t)DM * DI],     g_wol[(size_t)DM * DI];
__device__ float         g_xi [(size_t)MROWS * DI];
__device__ __nv_bfloat16 g_xih[(size_t)MROWS * DI],  g_xil[(size_t)MROWS * DI];
__device__ float         g_sz [(size_t)MROWS * DI];
__device__ float         g_lam[(size_t)MROWS * DI];
__device__ float         g_v  [(size_t)MROWS * DI];
__device__ __nv_bfloat16 g_gh [(size_t)MROWS * DI],  g_gl [(size_t)MROWS * DI];
__device__ float         g_fcolA[DI];
// block-scan scratch
__device__ float g_Lam [(size_t)TOTBLK * RB * DI];
__device__ float g_Vt  [(size_t)TOTBLK * RB * DI];
__device__ float g_Wh  [(size_t)TOTBLK * RB * DI];
__device__ float g_CumU[(size_t)TOTBLK * RB * DI];
__device__ float g_MT  [(size_t)TOTBLK * RB * RB];
__device__ float g_crow[(size_t)TOTBLK * RB];
__device__ float g_h0e [(size_t)TOTBLK * DI];
__device__ int   g_flag[TOTBLK];

// ---------------- helpers ------------------------------------------------------
__device__ __forceinline__ uint32_t smem_u32(const void* p) {
    uint32_t a;
    asm("{ .reg .u64 t; cvta.to.shared.u64 t, %1; cvt.u32.u64 %0, t; }" : "=r"(a) : "l"(p));
    return a;
}
__device__ __forceinline__ void cp16(uint32_t dst, const void* src) {
    asm volatile("cp.async.cg.shared.global [%0], [%1], 16;" :: "r"(dst), "l"(src));
}
#define CP_COMMIT() asm volatile("cp.async.commit_group;" ::: "memory")
#define CP_WAIT(n)  asm volatile("cp.async.wait_group %0;" :: "n"(n) : "memory")

__device__ __forceinline__ void mma_bf16(float* c, const uint32_t* a, const uint32_t* b) {
    asm volatile(
        "mma.sync.aligned.m16n8k16.row.col.f32.bf16.bf16.f32 "
        "{%0,%1,%2,%3}, {%4,%5,%6,%7}, {%8,%9}, {%0,%1,%2,%3};"
        : "+f"(c[0]), "+f"(c[1]), "+f"(c[2]), "+f"(c[3])
        : "r"(a[0]), "r"(a[1]), "r"(a[2]), "r"(a[3]), "r"(b[0]), "r"(b[1]));
}
#define LDSM_X4(r, addr) \
    asm volatile("ldmatrix.sync.aligned.m8n8.x4.shared.b16 {%0,%1,%2,%3}, [%4];" \
        : "=r"((r)[0]), "=r"((r)[1]), "=r"((r)[2]), "=r"((r)[3]) : "r"(addr))

__device__ __forceinline__ void split2(float a, float b, uint32_t& hv, uint32_t& lv) {
    __nv_bfloat162 h = __float22bfloat162_rn(make_float2(a, b));
    float2 hf = __bfloat1622float2(h);
    __nv_bfloat162 l = __float22bfloat162_rn(make_float2(a - hf.x, b - hf.y));
    hv = *(uint32_t*)&h; lv = *(uint32_t*)&l;
}

// ---------------- mega pre-pass (splits only) -----------------------------------
__global__ __launch_bounds__(256) void mega_pre(
    const float* __restrict__ x,    __nv_bfloat16* __restrict__ xh,   __nv_bfloat16* __restrict__ xl,
    const float* __restrict__ Win,  __nv_bfloat16* __restrict__ winh, __nv_bfloat16* __restrict__ winl,
    const float* __restrict__ Wl,   __nv_bfloat16* __restrict__ wlh,  __nv_bfloat16* __restrict__ wll,
    const float* __restrict__ Wv,   __nv_bfloat16* __restrict__ wvh,  __nv_bfloat16* __restrict__ wvl,
    const float* __restrict__ Wout, __nv_bfloat16* __restrict__ woh,  __nv_bfloat16* __restrict__ wol)
{
    const int seg = blockIdx.y;
    const int tid = threadIdx.x;
    const float* src; __nv_bfloat16 *hi, *lo; int n;
    switch (seg) {
        case 0: src = x;    hi = xh;   lo = xl;   n = MROWS * DM; break;
        case 1: src = Win;  hi = winh; lo = winl; n = DX * DM;    break;
        case 2: src = Wl;   hi = wlh;  lo = wll;  n = DI * DI;    break;
        case 3: src = Wv;   hi = wvh;  lo = wvl;  n = DI * DI;    break;
        default:src = Wout; hi = woh;  lo = wol;  n = DM * DI;    break;
    }
    const int i = (blockIdx.x * 256 + tid) * 4;
    if (i >= n) return;
    float4 f = *(const float4*)(src + i);
    uint32_t h0, l0, h1, l1;
    split2(f.x, f.y, h0, l0);
    split2(f.z, f.w, h1, l1);
    *(uint2*)(hi + i) = make_uint2(h0, h1);
    *(uint2*)(lo + i) = make_uint2(l0, l1);
}

// fcol + flag reset (flags consumed by scan_fused later in the same stream/graph)
__global__ void fcol_kernel(const float* __restrict__ omega, float* __restrict__ fcol) {
    int i = blockIdx.x * 256 + threadIdx.x;
    if (i < DI) fcol[i] = -8.0f * log1pf(__expf(omega[i]));
    if (blockIdx.x == 0 && threadIdx.x < TOTBLK) g_flag[threadIdx.x] = 0;
}

// ---------------- NT GEMM on pre-split operands (512 thr, 16 warps 32x32) --------
// trm0/trm1: number of split products (3 = AhBh+AhBl+AlBh, 2 = AhBh+AhBl) per z
__global__ __launch_bounds__(GT, 1) void gemm_ps(
    const __nv_bfloat16* __restrict__ Ahg, const __nv_bfloat16* __restrict__ Alg, int lda,
    const __nv_bfloat16* __restrict__ Bhg, const __nv_bfloat16* __restrict__ Blg,
    const __nv_bfloat16* __restrict__ Bhg2, const __nv_bfloat16* __restrict__ Blg2, int ldb,
    int K,
    float* __restrict__ C0, float* __restrict__ C1, int ldc,
    const float* __restrict__ bias, const float* __restrict__ bias2,
    const float* __restrict__ fcolg,
    __nv_bfloat16* __restrict__ Chi, __nv_bfloat16* __restrict__ Clo,
    float* __restrict__ Csz, int mode, int mode2, int trm0, int trm1)
{
    extern __shared__ char smraw[];
    const uint32_t smem_u = smem_u32(smraw);
    float* bias_s = (float*)(smraw + NSTAGE * STAGE_BYTES);
    float* fcol_s = bias_s + 128;

    const int tid = threadIdx.x;
    const int wid = tid >> 5, lane = tid & 31;
    const int g = lane >> 2, tq = lane & 3;
    const int wm = wid >> 2, wn = wid & 3;
    const int rowBase = blockIdx.y * 128;
    const int colBase = blockIdx.x * 128;

    const __nv_bfloat16* Bh_ = Bhg; const __nv_bfloat16* Bl_ = Blg;
    const float* biasp = bias; float* Cp = C0; int md = mode;
    bool t3 = (trm0 == 3);
    if (blockIdx.z == 1) { Bh_ = Bhg2; Bl_ = Blg2; biasp = bias2; Cp = C1; md = mode2; t3 = (trm1 == 3); }

    if (tid < 128) {
        int c = colBase + tid;
        bias_s[tid] = biasp ? biasp[c] : 0.f;
        fcol_s[tid] = (md == 1) ? fcolg[c] : 0.f;
    }

    const int nc = K / BKC;

    const int frow = tid >> 2, fseg = tid & 3;
    auto fill = [&](int c) {
        const uint32_t sb = smem_u + (uint32_t)(c % NSTAGE) * STAGE_BYTES;
        const uint32_t so = (uint32_t)(frow * PITCH + fseg * 8) * 2;
        const size_t ga = (size_t)(rowBase + frow) * lda + c * BKC + fseg * 8;
        const size_t gb = (size_t)(colBase + frow) * ldb + c * BKC + fseg * 8;
        cp16(sb + 0 * TILE_BYTES + so, Ahg + ga);
        cp16(sb + 1 * TILE_BYTES + so, Alg + ga);
        cp16(sb + 2 * TILE_BYTES + so, Bh_ + gb);
        cp16(sb + 3 * TILE_BYTES + so, Bl_ + gb);
        CP_COMMIT();
    };

    fill(0);
    fill(1);

    float acc[2][4][4];
    #pragma unroll
    for (int mt = 0; mt < 2; mt++)
        #pragma unroll
        for (int nt = 0; nt < 4; nt++)
            #pragma unroll
            for (int j = 0; j < 4; j++) acc[mt][nt][j] = 0.f;

    const int lr = lane & 15, lcq = (lane >> 4) << 3;

    for (int c = 0; c < nc; c++) {
        if (c + 2 < nc) fill(c + 2); else CP_COMMIT();
        CP_WAIT(2);
        __syncthreads();

        const uint32_t ub = smem_u + (uint32_t)(c % NSTAGE) * STAGE_BYTES;
        const uint32_t uAh = ub, uAl = ub + TILE_BYTES;
        const uint32_t uBh = ub + 2 * TILE_BYTES, uBl = ub + 3 * TILE_BYTES;

        #pragma unroll
        for (int kk = 0; kk < 2; kk++) {
            const int kc = kk * 16;
            uint32_t ah[2][4], al[2][4], bh[2][4], bl[2][4];
            #pragma unroll
            for (int mt = 0; mt < 2; mt++) {
                const uint32_t off = (uint32_t)(((wm * 32 + mt * 16 + lr) * PITCH + kc + lcq) * 2);
                LDSM_X4(ah[mt], uAh + off);
            }
            #pragma unroll
            for (int p = 0; p < 2; p++) {
                const uint32_t off = (uint32_t)(((wn * 32 + p * 16 + lr) * PITCH + kc + lcq) * 2);
                LDSM_X4(bh[p], uBh + off);
                LDSM_X4(bl[p], uBl + off);
            }
            uint32_t bH[4][2] = {{bh[0][0], bh[0][2]}, {bh[0][1], bh[0][3]},
                                 {bh[1][0], bh[1][2]}, {bh[1][1], bh[1][3]}};
            uint32_t bL[4][2] = {{bl[0][0], bl[0][2]}, {bl[0][1], bl[0][3]},
                                 {bl[1][0], bl[1][2]}, {bl[1][1], bl[1][3]}};
            #pragma unroll
            for (int mt = 0; mt < 2; mt++)
                #pragma unroll
                for (int nt = 0; nt < 4; nt++)
                    mma_bf16(acc[mt][nt], ah[mt], bH[nt]);
            #pragma unroll
            for (int mt = 0; mt < 2; mt++)
                #pragma unroll
                for (int nt = 0; nt < 4; nt++)
                    mma_bf16(acc[mt][nt], ah[mt], bL[nt]);
            if (t3) {
                #pragma unroll
                for (int mt = 0; mt < 2; mt++) {
                    const uint32_t off = (uint32_t)(((wm * 32 + mt * 16 + lr) * PITCH + kc + lcq) * 2);
                    LDSM_X4(al[mt], uAl + off);
                }
                #pragma unroll
                for (int mt = 0; mt < 2; mt++)
                    #pragma unroll
                    for (int nt = 0; nt < 4; nt++)
                        mma_bf16(acc[mt][nt], al[mt], bH[nt]);
            }
        }
    }

    const bool isxi = (md == 2) && (colBase < DI);
    const bool isz  = (md == 2) && (colBase >= DI);
    #pragma unroll
    for (int mt = 0; mt < 2; mt++) {
        const int r0 = rowBase + wm * 32 + mt * 16 + g;
        #pragma unroll
        for (int nt = 0; nt < 4; nt++) {
            const int col = wn * 32 + nt * 8 + tq * 2;
            float v0 = acc[mt][nt][0] + bias_s[col];
            float v1 = acc[mt][nt][1] + bias_s[col + 1];
            float v2 = acc[mt][nt][2] + bias_s[col];
            float v3 = acc[mt][nt][3] + bias_s[col + 1];
            if (md == 1) {
                const float f0 = fcol_s[col], f1 = fcol_s[col + 1];
                v0 = __expf(f0 * __frcp_rn(1.0f + __expf(-v0)));
                v1 = __expf(f1 * __frcp_rn(1.0f + __expf(-v1)));
                v2 = __expf(f0 * __frcp_rn(1.0f + __expf(-v2)));
                v3 = __expf(f1 * __frcp_rn(1.0f + __expf(-v3)));
            }
            if (isz) {
                const int cc = colBase - DI + col;
                float s0 = v0 * __frcp_rn(1.0f + __expf(-v0));
                float s1 = v1 * __frcp_rn(1.0f + __expf(-v1));
                float s2 = v2 * __frcp_rn(1.0f + __expf(-v2));
                float s3 = v3 * __frcp_rn(1.0f + __expf(-v3));
                *(float2*)(Csz + (size_t)r0 * DI + cc)       = make_float2(s0, s1);
                *(float2*)(Csz + (size_t)(r0 + 8) * DI + cc) = make_float2(s2, s3);
            } else {
                const int cc = colBase + col;
                *(float2*)(Cp + (size_t)r0 * ldc + cc)       = make_float2(v0, v1);
                *(float2*)(Cp + (size_t)(r0 + 8) * ldc + cc) = make_float2(v2, v3);
                if (isxi) {
                    uint32_t h0, l0, h1, l1;
                    split2(v0, v1, h0, l0);
                    split2(v2, v3, h1, l1);
                    *(uint32_t*)(Chi + (size_t)r0 * DI + cc)       = h0;
                    *(uint32_t*)(Clo + (size_t)r0 * DI + cc)       = l0;
                    *(uint32_t*)(Chi + (size_t)(r0 + 8) * DI + cc) = h1;
                    *(uint32_t*)(Clo + (size_t)(r0 + 8) * DI + cc) = l1;
                }
            }
        }
    }
}

// ---------------- scan phase A: per-block WY factors (round-12, correct) ---------
__global__ __launch_bounds__(512, 1) void scan_prep(
    const float* __restrict__ xi, const float* __restrict__ lam,
    const float* __restrict__ v)
{
    extern __shared__ float sa[];
    float* Gs  = sa;
    float* As  = Gs + RB * 65;
    float* Bs  = As + RB * PTCH;
    float* svs = Bs + RB * PTCH;

    const int blk = blockIdx.x;
    const int b = blk >> 5, n = blk & 31;
    const int t0 = n * 64 + 1;
    const int J = (n == 31) ? 63 : 64;
    const int tid = threadIdx.x;
    const int lane = tid & 31, wrp = tid >> 5;

    const float* lamb = lam + (size_t)b * TT * DI;
    const float* vb   = v   + (size_t)b * TT * DI;
    const float* xib  = xi  + (size_t)b * TT * DI;
    const size_t base = (size_t)blk * RB * DI;

    for (int r = wrp; r < RB; r += 16) {
        float s = 0.f;
        if (r < J) {
            const float4* vr = (const float4*)(vb + (size_t)(t0 + r) * DI);
            #pragma unroll
            for (int i = 0; i < 16; i++) {
                float4 a4 = vr[lane + i * 32];
                s += a4.x * a4.x + a4.y * a4.y + a4.z * a4.z + a4.w * a4.w;
            }
            #pragma unroll
            for (int o = 16; o; o >>= 1) s += __shfl_xor_sync(~0u, s, o);
        }
        if (lane == 0) svs[r] = (r < J) ? (2.0f / s) : 0.f;
    }
    __syncthreads();

    {
        const int c0 = tid * 4;
        float4 lp = make_float4(1.f, 1.f, 1.f, 1.f);
        float4 ip = make_float4(1.f, 1.f, 1.f, 1.f);
        float4 cu = make_float4(0.f, 0.f, 0.f, 0.f);
        for (int j = 0; j < J; j++) {
            const int t = t0 + j;
            const float4 la = *(const float4*)(lamb + (size_t)t * DI + c0);
            const float4 vv = *(const float4*)(vb   + (size_t)t * DI + c0);
            const float4 xx = *(const float4*)(xib  + (size_t)t * DI + c0);
            const float sj = svs[j];
            float4 vt, wh;
            vt.x = vv.x * lp.x; vt.y = vv.y * lp.y; vt.z = vv.z * lp.z; vt.w = vv.w * lp.w;
            wh.x = sj * vv.x * ip.x; wh.y = sj * vv.y * ip.y;
            wh.z = sj * vv.z * ip.z; wh.w = sj * vv.w * ip.w;
            lp.x *= la.x; lp.y *= la.y; lp.z *= la.z; lp.w *= la.w;
            ip.x *= __frcp_rn(la.x); ip.y *= __frcp_rn(la.y);
            ip.z *= __frcp_rn(la.z); ip.w *= __frcp_rn(la.w);
            cu.x += (1.f - la.x) * xx.x * ip.x;
            cu.y += (1.f - la.y) * xx.y * ip.y;
            cu.z += (1.f - la.z) * xx.z * ip.z;
            cu.w += (1.f - la.w) * xx.w * ip.w;
            const size_t o = base + (size_t)j * DI + c0;
            *(float4*)(g_Vt   + o) = vt;
            *(float4*)(g_Wh   + o) = wh;
            *(float4*)(g_Lam  + o) = lp;
            *(float4*)(g_CumU + o) = cu;
        }
        const float4 z4 = make_float4(0.f, 0.f, 0.f, 0.f);
        for (int j = J; j < RB; j++) {
            const size_t o = base + (size_t)j * DI + c0;
            *(float4*)(g_Vt + o) = z4;
            *(float4*)(g_Wh + o) = z4;
        }
    }
    __syncthreads();

    const int act  = (tid < 128);
    const int row0 = (tid >> 3) * 4;
    const int col0 = (tid & 7) * 8;
    {
        float acc[4][8];
        #pragma unroll
        for (int r = 0; r < 4; r++)
            #pragma unroll
            for (int e = 0; e < 8; e++) acc[r][e] = 0.f;

        for (int ch = 0; ch < DI; ch += 64) {
            for (int u = tid; u < 64 * 16; u += 512) {
                const int r = u >> 4, q = (u & 15) * 4;
                const float4 a4 = *(const float4*)(g_Vt + base + (size_t)r * DI + ch + q);
                *(float4*)(As + r * PTCH + q) = a4;
                const float4 b4 = *(const float4*)(g_Wh + base + (size_t)r * DI + ch + q);
                Bs[(q + 0) * PTCH + r] = b4.x;
                Bs[(q + 1) * PTCH + r] = b4.y;
                Bs[(q + 2) * PTCH + r] = b4.z;
                Bs[(q + 3) * PTCH + r] = b4.w;
            }
            __syncthreads();
            if (act) {
                #pragma unroll 4
                for (int k4 = 0; k4 < 16; k4++) {
                    float av[4][4];
                    #pragma unroll
                    for (int r = 0; r < 4; r++)
                        *(float4*)av[r] = *(const float4*)(As + (row0 + r) * PTCH + k4 * 4);
                    #pragma unroll
                    for (int kk = 0; kk < 4; kk++) {
                        const int k = k4 * 4 + kk;
                        float bv[8];
                        *(float4*)&bv[0] = *(const float4*)(Bs + k * PTCH + col0);
                        *(float4*)&bv[4] = *(const float4*)(Bs + k * PTCH + col0 + 4);
                        #pragma unroll
                        for (int r = 0; r < 4; r++)
                            #pragma unroll
                            for (int e = 0; e < 8; e++)
                                acc[r][e] += av[r][kk] * bv[e];
                    }
                }
            }
            __syncthreads();
        }
        if (act) {
            #pragma unroll
            for (int r = 0; r < 4; r++)
                #pragma unroll
                for (int e = 0; e < 8; e++) {
                    const int rr = row0 + r, cc = col0 + e;
                    Gs[rr * 65 + cc] = (cc < rr) ? acc[r][e] : 0.f;
                }
        }
    }

    for (int r = wrp; r < RB; r += 16) {
        float s = 0.f;
        if (r >= 1 && r < J) {
            const float4* a4p = (const float4*)(g_Vt + base + (size_t)r * DI);
            const float4* b4p = (const float4*)(g_CumU + base + (size_t)(r - 1) * DI);
            for (int i = lane; i < 512; i += 32) {
                const float4 a4 = a4p[i];
                const float4 b4 = b4p[i];
                s += a4.x * b4.x + a4.y * b4.y + a4.z * b4.z + a4.w * b4.w;
            }
            #pragma unroll
            for (int o = 16; o; o >>= 1) s += __shfl_xor_sync(~0u, s, o);
        }
        if (lane == 0) g_crow[blk * RB + r] = (r >= 1 && r < J) ? s : 0.f;
    }
    __syncthreads();

    for (int idx = tid; idx < RB * RB; idx += 512) {
        const int r = idx >> 6, c = idx & 63;
        const float gv = (c < r) ? Gs[r * 65 + c] : 0.f;
        As[r * PTCH + c] = -gv;
        Bs[r * PTCH + c] = (r == c) ? 1.f : 0.f;
    }
    __syncthreads();
    for (int m = 0; m < 6; m++) {
        {
            float t[4][8];
            #pragma unroll
            for (int r = 0; r < 4; r++)
                #pragma unroll
                for (int e = 0; e < 8; e++) t[r][e] = 0.f;
            if (act) {
                #pragma unroll 4
                for (int k4 = 0; k4 < 16; k4++) {
                    float av[4][4];
                    #pragma unroll
                    for (int r = 0; r < 4; r++)
                        *(float4*)av[r] = *(const float4*)(As + (row0 + r) * PTCH + k4 * 4);
                    #pragma unroll
                    for (int kk = 0; kk < 4; kk++) {
                        const int k = k4 * 4 + kk;
                        float bv[8];
                        *(float4*)&bv[0] = *(const float4*)(Bs + k * PTCH + col0);
                        *(float4*)&bv[4] = *(const float4*)(Bs + k * PTCH + col0 + 4);
                        #pragma unroll
                        for (int r = 0; r < 4; r++)
                            #pragma unroll
                            for (int e = 0; e < 8; e++)
                                t[r][e] += av[r][kk] * bv[e];
                    }
                }
            }
            __syncthreads();
            if (act) {
                #pragma unroll
                for (int r = 0; r < 4; r++) {
                    float4 s0 = *(const float4*)(Bs + (row0 + r) * PTCH + col0);
                    float4 s1 = *(const float4*)(Bs + (row0 + r) * PTCH + col0 + 4);
                    s0.x += t[r][0]; s0.y += t[r][1]; s0.z += t[r][2]; s0.w += t[r][3];
                    s1.x += t[r][4]; s1.y += t[r][5]; s1.z += t[r][6]; s1.w += t[r][7];
                    *(float4*)(Bs + (row0 + r) * PTCH + col0)     = s0;
                    *(float4*)(Bs + (row0 + r) * PTCH + col0 + 4) = s1;
                }
            }
            __syncthreads();
        }
        if (m < 5) {
            float t[4][8];
            #pragma unroll
            for (int r = 0; r < 4; r++)
                #pragma unroll
                for (int e = 0; e < 8; e++) t[r][e] = 0.f;
            if (act) {
                #pragma unroll 4
                for (int k4 = 0; k4 < 16; k4++) {
                    float av[4][4];
                    #pragma unroll
                    for (int r = 0; r < 4; r++)
                        *(float4*)av[r] = *(const float4*)(As + (row0 + r) * PTCH + k4 * 4);
                    #pragma unroll
                    for (int kk = 0; kk < 4; kk++) {
                        const int k = k4 * 4 + kk;
                        float bv[8];
                        *(float4*)&bv[0] = *(const float4*)(As + k * PTCH + col0);
                        *(float4*)&bv[4] = *(const float4*)(As + k * PTCH + col0 + 4);
                        #pragma unroll
                        for (int r = 0; r < 4; r++)
                            #pragma unroll
                            for (int e = 0; e < 8; e++)
                                t[r][e] += av[r][kk] * bv[e];
                    }
                }
            }
            __syncthreads();
            if (act) {
                #pragma unroll
                for (int r = 0; r < 4; r++) {
                    *(float4*)(As + (row0 + r) * PTCH + col0)     = *(float4*)&t[r][0];
                    *(float4*)(As + (row0 + r) * PTCH + col0 + 4) = *(float4*)&t[r][4];
                }
            }
            __syncthreads();
        }
    }
    for (int idx = tid; idx < RB * RB; idx += 512) {
        const int i = idx >> 6, j = idx & 63;
        g_MT[(size_t)blk * RB * RB + idx] = Bs[j * PTCH + i];
    }
}

// ---------------- scan phase B: fused chain+recon, flag-pipelined over blocks ----
// CTA blk handles (batch b = blk>>5, block n = blk&31). Sequencing: CTA waits on
// g_flag[blk] (set by predecessor after writing g_h0e[blk]); n==0 starts free.
// Fast path per CTA: f = Vt*h0 + crow ; a = M f ; ws = Wh^T a ; h_exit -> signal.
// Then full reconstruction (Wh re-read is L2-hot) in the successor's shadow.
__global__ __launch_bounds__(512, 1) void scan_fused(
    const float* __restrict__ xi, const float* __restrict__ sz,
    __nv_bfloat16* __restrict__ gh, __nv_bfloat16* __restrict__ gl)
{
    __shared__ float MTs[RB * RB];
    __shared__ float h0s[DI];
    __shared__ float fs[RB];
    __shared__ float as[RB];

    const int blk = blockIdx.x;
    const int b = blk >> 5, n = blk & 31;
    const int t0 = n * 64 + 1;
    const int J = (n == 31) ? 63 : 64;
    const int tid = threadIdx.x;
    const int lane = tid & 31, wrp = tid >> 5;
    const int c0 = tid * 4;
    const size_t base = (size_t)blk * RB * DI;

    const float* xib = xi + (size_t)b * TT * DI;
    const float* szb = sz + (size_t)b * TT * DI;
    __nv_bfloat16* ghb = gh + (size_t)b * TT * DI;
    __nv_bfloat16* glb = gl + (size_t)b * TT * DI;

    // load MT while (possibly) waiting
    for (int idx = tid; idx < RB * RB; idx += 512)
        MTs[idx] = g_MT[(size_t)blk * RB * RB + idx];

    // entry state h0
    float4 h0;
    if (n == 0) {
        h0 = *(const float4*)(xib + c0);
        // t=0 output
        const float4 s0 = *(const float4*)(szb + c0);
        uint32_t a0, b0, a1, b1;
        split2(s0.x * h0.x, s0.y * h0.y, a0, b0);
        split2(s0.z * h0.z, s0.w * h0.w, a1, b1);
        *(uint2*)(ghb + c0) = make_uint2(a0, a1);
        *(uint2*)(glb + c0) = make_uint2(b0, b1);
    } else {
        if (tid == 0) {
            while (atomicAdd(&g_flag[blk], 0) == 0) { __nanosleep(100); }
            __threadfence();
        }
        __syncthreads();
        h0 = *(const float4*)(g_h0e + (size_t)blk * DI + c0);
    }
    *(float4*)(h0s + c0) = h0;
    __syncthreads();

    // f_j = Vt_j . h0 + crow_j  (16 warps x 4 rows each)
    for (int r = wrp; r < RB; r += 16) {
        float s = 0.f;
        if (r < J) {
            const float4* a4p = (const float4*)(g_Vt + base + (size_t)r * DI);
            #pragma unroll
            for (int i = 0; i < 16; i++) {
                const int ci = lane + i * 32;
                const float4 a4 = a4p[ci];
                const float4 h4 = *(const float4*)(h0s + ci * 4);
                s += a4.x * h4.x + a4.y * h4.y + a4.z * h4.z + a4.w * h4.w;
            }
            #pragma unroll
            for (int o = 16; o; o >>= 1) s += __shfl_xor_sync(~0u, s, o);
        }
        if (lane == 0) fs[r] = s + g_crow[blk * RB + r];
    }
    __syncthreads();

    // a = M f
    if (tid < RB) {
        float s = 0.f;
        #pragma unroll 8
        for (int i = 0; i < RB; i++)
            s += MTs[i * RB + tid] * fs[i];
        as[tid] = s;
    }
    __syncthreads();

    // exit state: ws = Wh^T a ; h_exit = Lam_{J-1}*(h0 + CumU_{J-1} - ws); signal
    if (n < 31) {
        float4 wsx = make_float4(0.f, 0.f, 0.f, 0.f);
        #pragma unroll 8
        for (int j = 0; j < RB; j++) {
            const float4 wh = *(const float4*)(g_Wh + base + (size_t)j * DI + c0);
            const float aj = as[j];
            wsx.x += wh.x * aj; wsx.y += wh.y * aj;
            wsx.z += wh.z * aj; wsx.w += wh.w * aj;
        }
        const float4 la = *(const float4*)(g_Lam  + base + (size_t)(J - 1) * DI + c0);
        const float4 cu = *(const float4*)(g_CumU + base + (size_t)(J - 1) * DI + c0);
        float4 he;
        he.x = la.x * (h0.x + cu.x - wsx.x);
        he.y = la.y * (h0.y + cu.y - wsx.y);
        he.z = la.z * (h0.z + cu.z - wsx.z);
        he.w = la.w * (h0.w + cu.w - wsx.w);
        *(float4*)(g_h0e + (size_t)(blk + 1) * DI + c0) = he;
        __threadfence();
        __syncthreads();
        if (tid == 0) atomicExch(&g_flag[blk + 1], 1);
    }

    // reconstruction (Wh re-read is L2-hot)
    float4 ws = make_float4(0.f, 0.f, 0.f, 0.f);
    for (int j = 0; j < J; j++) {
        const size_t o = base + (size_t)j * DI + c0;
        const float4 wh = *(const float4*)(g_Wh + o);
        const float4 cu = *(const float4*)(g_CumU + o);
        const float4 la = *(const float4*)(g_Lam + o);
        const float4 s4 = *(const float4*)(szb + (size_t)(t0 + j) * DI + c0);
        const float aj = as[j];
        ws.x += wh.x * aj; ws.y += wh.y * aj;
        ws.z += wh.z * aj; ws.w += wh.w * aj;
        float4 hj;
        hj.x = la.x * (h0.x + cu.x - ws.x);
        hj.y = la.y * (h0.y + cu.y - ws.y);
        hj.z = la.z * (h0.z + cu.z - ws.z);
        hj.w = la.w * (h0.w + cu.w - ws.w);
        uint32_t a0, b0, a1, b1;
        split2(s4.x * hj.x, s4.y * hj.y, a0, b0);
        split2(s4.z * hj.z, s4.w * hj.w, a1, b1);
        const size_t og = (size_t)(t0 + j) * DI + c0;
        *(uint2*)(ghb + og) = make_uint2(a0, a1);
        *(uint2*)(glb + og) = make_uint2(b0, b1);
    }
}

// ---------------- launcher ----------------------------------------------------------
extern "C" void kernel_launch(void* const* d_in, const int* in_sizes, int n_in,
                              void* d_out, int out_size)
{
    const float* x     = (const float*)d_in[0];
    const float* omega = (const float*)d_in[1];
    const float* Win   = (const float*)d_in[2];
    const float* Wl    = (const float*)d_in[3];
    const float* bl    = (const float*)d_in[4];
    const float* Wv    = (const float*)d_in[5];
    const float* bv    = (const float*)d_in[6];
    const float* Wout  = (const float*)d_in[7];
    float* out = (float*)d_out;

    __nv_bfloat16 *xh, *xl, *winh, *winl, *wlh, *wll, *wvh, *wvl, *woh, *wol;
    __nv_bfloat16 *xih, *xil, *gh, *gl;
    float *xi, *szp, *lam, *v, *fcol;
    cudaGetSymbolAddress((void**)&xh,   g_xh);   cudaGetSymbolAddress((void**)&xl,   g_xl);
    cudaGetSymbolAddress((void**)&winh, g_winh); cudaGetSymbolAddress((void**)&winl, g_winl);
    cudaGetSymbolAddress((void**)&wlh,  g_wlh);  cudaGetSymbolAddress((void**)&wll,  g_wll);
    cudaGetSymbolAddress((void**)&wvh,  g_wvh);  cudaGetSymbolAddress((void**)&wvl,  g_wvl);
    cudaGetSymbolAddress((void**)&woh,  g_woh);  cudaGetSymbolAddress((void**)&wol,  g_wol);
    cudaGetSymbolAddress((void**)&xi,   g_xi);
    cudaGetSymbolAddress((void**)&xih,  g_xih);  cudaGetSymbolAddress((void**)&xil,  g_xil);
    cudaGetSymbolAddress((void**)&szp,  g_sz);
    cudaGetSymbolAddress((void**)&lam,  g_lam);  cudaGetSymbolAddress((void**)&v,    g_v);
    cudaGetSymbolAddress((void**)&gh,   g_gh);   cudaGetSymbolAddress((void**)&gl,   g_gl);
    cudaGetSymbolAddress((void**)&fcol, g_fcolA);

    cudaFuncSetAttribute(gemm_ps, cudaFuncAttributeMaxDynamicSharedMemorySize, GEMM_SMEM);
    cudaFuncSetAttribute(scan_prep, cudaFuncAttributeMaxDynamicSharedMemorySize, SMEMA);

    // 0) splits
    mega_pre<<<dim3((MROWS * DM) / 1024, 5), 256>>>(
        x, xh, xl, Win, winh, winl, Wl, wlh, wll, Wv, wvh, wvl, Wout, woh, wol);

    // 1) GEMM1: xz -> xi (fp32 + split) | silu(z)   [3-term]
    gemm_ps<<<dim3(DX / 128, MROWS / 128, 1), GT, GEMM_SMEM>>>(
        xh, xl, DM, winh, winl, nullptr, nullptr, DM, DM,
        xi, nullptr, DI, nullptr, nullptr, fcol, xih, xil, szp, 2, 2, 3, 3);

    // 2) fcol + flag reset
    fcol_kernel<<<DI / 256, 256>>>(omega, fcol);

    // 3) GEMM2+3 fused (PROFILED): z=0 -> lam [2-term], z=1 -> v [3-term]
    gemm_ps<<<dim3(DI / 128, MROWS / 128, 2), GT, GEMM_SMEM>>>(
        xih, xil, DI, wlh, wll, wvh, wvl, DI, DI,
        lam, v, DI, bl, bv, fcol, nullptr, nullptr, nullptr, 1, 0, 2, 3);

    // 4) scan prep
    scan_prep<<<TOTBLK, 512, SMEMA>>>(xi, lam, v);

    // 5) fused chain+recon (flag-pipelined, 128 co-resident CTAs)
    scan_fused<<<TOTBLK, 512>>>(xi, szp, gh, gl);

    // 6) GEMM4: out = g @ Wout^T   [3-term]
    gemm_ps<<<dim3(DM / 128, MROWS / 128, 1), GT, GEMM_SMEM>>>(
        gh, gl, DI, woh, wol, nullptr, nullptr, DI, DI,
        out, nullptr, DM, nullptr, nullptr, fcol, nullptr, nullptr, nullptr, 0, 0, 3, 3);
}

// round 16
// speedup vs baseline: 1.0868x; 1.0868x over previous
#include <cuda_runtime.h>
#include <cuda_bf16.h>
#include <cuda_fp16.h>
#include <cstdint>
#include <cstddef>

// Problem constants
#define BB   4
#define TT   2048
#define DM   1024
#define DI   2048
#define DX   4096
#define MROWS (BB*TT)   // 8192

// GEMM tiling (128x128 CTA, 16 warps of 32x32)
#define BKC   32
#define PITCH 40
#define TILE_BYTES (128*PITCH*2)
#define STAGE_BYTES (4*TILE_BYTES)
#define NSTAGE 4
#define GEMM_SMEM (NSTAGE*STAGE_BYTES + 1024)
#define F16_SMEM  (NSTAGE*2*TILE_BYTES)
#define GT    512

// Block-scan config
#define RB    64
#define NBLK  32
#define TOTBLK 128
#define PTCH  68
#define SMEMA ((RB*65 + 2*RB*PTCH + RB)*4)

// ---------------- scratch ----------------------------------------------------
__device__ __nv_bfloat16 g_xh [(size_t)MROWS * DM],  g_xl [(size_t)MROWS * DM];
__device__ __nv_bfloat16 g_winh[(size_t)DX * DM],    g_winl[(size_t)DX * DM];
__device__ __nv_bfloat16 g_wlh[(size_t)DI * DI],     g_wll[(size_t)DI * DI];
__device__ __nv_bfloat16 g_wvh[(size_t)DI * DI],     g_wvl[(size_t)DI * DI];
__device__ __half        g_wof[(size_t)DM * DI];
__device__ float         g_xi [(size_t)MROWS * DI];
__device__ __nv_bfloat16 g_xih[(size_t)MROWS * DI],  g_xil[(size_t)MROWS * DI];
__device__ float         g_sz [(size_t)MROWS * DI];
__device__ float         g_lam[(size_t)MROWS * DI];
__device__ float         g_v  [(size_t)MROWS * DI];
__device__ __half        g_gf [(size_t)MROWS * DI];
__device__ float         g_fcolA[DI];
// block-scan scratch
__device__ float g_Lam [(size_t)TOTBLK * RB * DI];
__device__ float g_Vt  [(size_t)TOTBLK * RB * DI];
__device__ float g_Wh  [(size_t)TOTBLK * RB * DI];
__device__ float g_CumU[(size_t)TOTBLK * RB * DI];
__device__ float g_MT  [(size_t)TOTBLK * RB * RB];
__device__ float g_crow[(size_t)TOTBLK * RB];
__device__ float g_h0e [(size_t)TOTBLK * DI];
__device__ float g_as  [(size_t)TOTBLK * RB];

// ---------------- helpers ------------------------------------------------------
__device__ __forceinline__ uint32_t smem_u32(const void* p) {
    uint32_t a;
    asm("{ .reg .u64 t; cvta.to.shared.u64 t, %1; cvt.u32.u64 %0, t; }" : "=r"(a) : "l"(p));
    return a;
}
__device__ __forceinline__ void cp16(uint32_t dst, const void* src) {
    asm volatile("cp.async.cg.shared.global [%0], [%1], 16;" :: "r"(dst), "l"(src));
}
#define CP_COMMIT() asm volatile("cp.async.commit_group;" ::: "memory")
#define CP_WAIT(n)  asm volatile("cp.async.wait_group %0;" :: "n"(n) : "memory")

__device__ __forceinline__ void mma_bf16(float* c, const uint32_t* a, const uint32_t* b) {
    asm volatile(
        "mma.sync.aligned.m16n8k16.row.col.f32.bf16.bf16.f32 "
        "{%0,%1,%2,%3}, {%4,%5,%6,%7}, {%8,%9}, {%0,%1,%2,%3};"
        : "+f"(c[0]), "+f"(c[1]), "+f"(c[2]), "+f"(c[3])
        : "r"(a[0]), "r"(a[1]), "r"(a[2]), "r"(a[3]), "r"(b[0]), "r"(b[1]));
}
__device__ __forceinline__ void mma_f16(float* c, const uint32_t* a, const uint32_t* b) {
    asm volatile(
        "mma.sync.aligned.m16n8k16.row.col.f32.f16.f16.f32 "
        "{%0,%1,%2,%3}, {%4,%5,%6,%7}, {%8,%9}, {%0,%1,%2,%3};"
        : "+f"(c[0]), "+f"(c[1]), "+f"(c[2]), "+f"(c[3])
        : "r"(a[0]), "r"(a[1]), "r"(a[2]), "r"(a[3]), "r"(b[0]), "r"(b[1]));
}
#define LDSM_X4(r, addr) \
    asm volatile("ldmatrix.sync.aligned.m8n8.x4.shared.b16 {%0,%1,%2,%3}, [%4];" \
        : "=r"((r)[0]), "=r"((r)[1]), "=r"((r)[2]), "=r"((r)[3]) : "r"(addr))

__device__ __forceinline__ void split2(float a, float b, uint32_t& hv, uint32_t& lv) {
    __nv_bfloat162 h = __float22bfloat162_rn(make_float2(a, b));
    float2 hf = __bfloat1622float2(h);
    __nv_bfloat162 l = __float22bfloat162_rn(make_float2(a - hf.x, b - hf.y));
    hv = *(uint32_t*)&h; lv = *(uint32_t*)&l;
}

// ---------------- mega pre-pass ---------------------------------------------------
// seg 0..3: fp32 -> bf16 hi/lo split; seg 4: Wout -> plain fp16
__global__ __launch_bounds__(256) void mega_pre(
    const float* __restrict__ x,    __nv_bfloat16* __restrict__ xh,   __nv_bfloat16* __restrict__ xl,
    const float* __restrict__ Win,  __nv_bfloat16* __restrict__ winh, __nv_bfloat16* __restrict__ winl,
    const float* __restrict__ Wl,   __nv_bfloat16* __restrict__ wlh,  __nv_bfloat16* __restrict__ wll,
    const float* __restrict__ Wv,   __nv_bfloat16* __restrict__ wvh,  __nv_bfloat16* __restrict__ wvl,
    const float* __restrict__ Wout, __half* __restrict__ wof)
{
    const int seg = blockIdx.y;
    const int tid = threadIdx.x;
    const int i = (blockIdx.x * 256 + tid) * 4;
    if (seg == 4) {
        if (i >= DM * DI) return;
        float4 f = *(const float4*)(Wout + i);
        __half2 p0 = __floats2half2_rn(f.x, f.y);
        __half2 p1 = __floats2half2_rn(f.z, f.w);
        *(uint2*)(wof + i) = make_uint2(*(uint32_t*)&p0, *(uint32_t*)&p1);
        return;
    }
    const float* src; __nv_bfloat16 *hi, *lo; int n;
    switch (seg) {
        case 0: src = x;    hi = xh;   lo = xl;   n = MROWS * DM; break;
        case 1: src = Win;  hi = winh; lo = winl; n = DX * DM;    break;
        case 2: src = Wl;   hi = wlh;  lo = wll;  n = DI * DI;    break;
        default:src = Wv;   hi = wvh;  lo = wvl;  n = DI * DI;    break;
    }
    if (i >= n) return;
    float4 f = *(const float4*)(src + i);
    uint32_t h0, l0, h1, l1;
    split2(f.x, f.y, h0, l0);
    split2(f.z, f.w, h1, l1);
    *(uint2*)(hi + i) = make_uint2(h0, h1);
    *(uint2*)(lo + i) = make_uint2(l0, l1);
}

__global__ void fcol_kernel(const float* __restrict__ omega, float* __restrict__ fcol) {
    int i = blockIdx.x * 256 + threadIdx.x;
    if (i < DI) fcol[i] = -8.0f * log1pf(__expf(omega[i]));
}

// ---------------- bf16 split NT GEMM (512 thr, 16 warps 32x32) --------------------
__global__ __launch_bounds__(GT, 1) void gemm_ps(
    const __nv_bfloat16* __restrict__ Ahg, const __nv_bfloat16* __restrict__ Alg, int lda,
    const __nv_bfloat16* __restrict__ Bhg, const __nv_bfloat16* __restrict__ Blg,
    const __nv_bfloat16* __restrict__ Bhg2, const __nv_bfloat16* __restrict__ Blg2, int ldb,
    int K,
    float* __restrict__ C0, float* __restrict__ C1, int ldc,
    const float* __restrict__ bias, const float* __restrict__ bias2,
    const float* __restrict__ fcolg,
    __nv_bfloat16* __restrict__ Chi, __nv_bfloat16* __restrict__ Clo,
    float* __restrict__ Csz, int mode, int mode2, int trm0, int trm1)
{
    extern __shared__ char smraw[];
    const uint32_t smem_u = smem_u32(smraw);
    float* bias_s = (float*)(smraw + NSTAGE * STAGE_BYTES);
    float* fcol_s = bias_s + 128;

    const int tid = threadIdx.x;
    const int wid = tid >> 5, lane = tid & 31;
    const int g = lane >> 2, tq = lane & 3;
    const int wm = wid >> 2, wn = wid & 3;
    const int rowBase = blockIdx.y * 128;
    const int colBase = blockIdx.x * 128;

    const __nv_bfloat16* Bh_ = Bhg; const __nv_bfloat16* Bl_ = Blg;
    const float* biasp = bias; float* Cp = C0; int md = mode;
    bool t3 = (trm0 == 3);
    if (blockIdx.z == 1) { Bh_ = Bhg2; Bl_ = Blg2; biasp = bias2; Cp = C1; md = mode2; t3 = (trm1 == 3); }

    if (tid < 128) {
        int c = colBase + tid;
        bias_s[tid] = biasp ? biasp[c] : 0.f;
        fcol_s[tid] = (md == 1) ? fcolg[c] : 0.f;
    }

    const int nc = K / BKC;

    const int frow = tid >> 2, fseg = tid & 3;
    auto fill = [&](int c) {
        const uint32_t sb = smem_u + (uint32_t)(c % NSTAGE) * STAGE_BYTES;
        const uint32_t so = (uint32_t)(frow * PITCH + fseg * 8) * 2;
        const size_t ga = (size_t)(rowBase + frow) * lda + c * BKC + fseg * 8;
        const size_t gb = (size_t)(colBase + frow) * ldb + c * BKC + fseg * 8;
        cp16(sb + 0 * TILE_BYTES + so, Ahg + ga);
        cp16(sb + 1 * TILE_BYTES + so, Alg + ga);
        cp16(sb + 2 * TILE_BYTES + so, Bh_ + gb);
        cp16(sb + 3 * TILE_BYTES + so, Bl_ + gb);
        CP_COMMIT();
    };

    fill(0);
    fill(1);

    float acc[2][4][4];
    #pragma unroll
    for (int mt = 0; mt < 2; mt++)
        #pragma unroll
        for (int nt = 0; nt < 4; nt++)
            #pragma unroll
            for (int j = 0; j < 4; j++) acc[mt][nt][j] = 0.f;

    const int lr = lane & 15, lcq = (lane >> 4) << 3;

    for (int c = 0; c < nc; c++) {
        if (c + 2 < nc) fill(c + 2); else CP_COMMIT();
        CP_WAIT(2);
        __syncthreads();

        const uint32_t ub = smem_u + (uint32_t)(c % NSTAGE) * STAGE_BYTES;
        const uint32_t uAh = ub, uAl = ub + TILE_BYTES;
        const uint32_t uBh = ub + 2 * TILE_BYTES, uBl = ub + 3 * TILE_BYTES;

        #pragma unroll
        for (int kk = 0; kk < 2; kk++) {
            const int kc = kk * 16;
            uint32_t ah[2][4], al[2][4], bh[2][4], bl[2][4];
            #pragma unroll
            for (int mt = 0; mt < 2; mt++) {
                const uint32_t off = (uint32_t)(((wm * 32 + mt * 16 + lr) * PITCH + kc + lcq) * 2);
                LDSM_X4(ah[mt], uAh + off);
            }
            #pragma unroll
            for (int p = 0; p < 2; p++) {
                const uint32_t off = (uint32_t)(((wn * 32 + p * 16 + lr) * PITCH + kc + lcq) * 2);
                LDSM_X4(bh[p], uBh + off);
                LDSM_X4(bl[p], uBl + off);
            }
            uint32_t bH[4][2] = {{bh[0][0], bh[0][2]}, {bh[0][1], bh[0][3]},
                                 {bh[1][0], bh[1][2]}, {bh[1][1], bh[1][3]}};
            uint32_t bL[4][2] = {{bl[0][0], bl[0][2]}, {bl[0][1], bl[0][3]},
                                 {bl[1][0], bl[1][2]}, {bl[1][1], bl[1][3]}};
            #pragma unroll
            for (int mt = 0; mt < 2; mt++)
                #pragma unroll
                for (int nt = 0; nt < 4; nt++)
                    mma_bf16(acc[mt][nt], ah[mt], bH[nt]);
            #pragma unroll
            for (int mt = 0; mt < 2; mt++)
                #pragma unroll
                for (int nt = 0; nt < 4; nt++)
                    mma_bf16(acc[mt][nt], ah[mt], bL[nt]);
            if (t3) {
                #pragma unroll
                for (int mt = 0; mt < 2; mt++) {
                    const uint32_t off = (uint32_t)(((wm * 32 + mt * 16 + lr) * PITCH + kc + lcq) * 2);
                    LDSM_X4(al[mt], uAl + off);
                }
                #pragma unroll
                for (int mt = 0; mt < 2; mt++)
                    #pragma unroll
                    for (int nt = 0; nt < 4; nt++)
                        mma_bf16(acc[mt][nt], al[mt], bH[nt]);
            }
        }
    }

    const bool isxi = (md == 2) && (colBase < DI);
    const bool isz  = (md == 2) && (colBase >= DI);
    #pragma unroll
    for (int mt = 0; mt < 2; mt++) {
        const int r0 = rowBase + wm * 32 + mt * 16 + g;
        #pragma unroll
        for (int nt = 0; nt < 4; nt++) {
            const int col = wn * 32 + nt * 8 + tq * 2;
            float v0 = acc[mt][nt][0] + bias_s[col];
            float v1 = acc[mt][nt][1] + bias_s[col + 1];
            float v2 = acc[mt][nt][2] + bias_s[col];
            float v3 = acc[mt][nt][3] + bias_s[col + 1];
            if (md == 1) {
                const float f0 = fcol_s[col], f1 = fcol_s[col + 1];
                v0 = __expf(f0 * __frcp_rn(1.0f + __expf(-v0)));
                v1 = __expf(f1 * __frcp_rn(1.0f + __expf(-v1)));
                v2 = __expf(f0 * __frcp_rn(1.0f + __expf(-v2)));
                v3 = __expf(f1 * __frcp_rn(1.0f + __expf(-v3)));
            }
            if (isz) {
                const int cc = colBase - DI + col;
                float s0 = v0 * __frcp_rn(1.0f + __expf(-v0));
                float s1 = v1 * __frcp_rn(1.0f + __expf(-v1));
                float s2 = v2 * __frcp_rn(1.0f + __expf(-v2));
                float s3 = v3 * __frcp_rn(1.0f + __expf(-v3));
                *(float2*)(Csz + (size_t)r0 * DI + cc)       = make_float2(s0, s1);
                *(float2*)(Csz + (size_t)(r0 + 8) * DI + cc) = make_float2(s2, s3);
            } else {
                const int cc = colBase + col;
                *(float2*)(Cp + (size_t)r0 * ldc + cc)       = make_float2(v0, v1);
                *(float2*)(Cp + (size_t)(r0 + 8) * ldc + cc) = make_float2(v2, v3);
                if (isxi) {
                    uint32_t h0, l0, h1, l1;
                    split2(v0, v1, h0, l0);
                    split2(v2, v3, h1, l1);
                    *(uint32_t*)(Chi + (size_t)r0 * DI + cc)       = h0;
                    *(uint32_t*)(Clo + (size_t)r0 * DI + cc)       = l0;
                    *(uint32_t*)(Chi + (size_t)(r0 + 8) * DI + cc) = h1;
                    *(uint32_t*)(Clo + (size_t)(r0 + 8) * DI + cc) = l1;
                }
            }
        }
    }
}

// ---------------- plain fp16 NT GEMM: C[M,N] = A[M,K] * B[N,K]^T ------------------
__global__ __launch_bounds__(GT, 1) void gemm_f16(
    const __half* __restrict__ A, int lda,
    const __half* __restrict__ B, int ldb, int K,
    float* __restrict__ C, int ldc)
{
    extern __shared__ char smraw[];
    const uint32_t smem_u = smem_u32(smraw);
    const int tid = threadIdx.x;
    const int wid = tid >> 5, lane = tid & 31;
    const int g = lane >> 2, tq = lane & 3;
    const int wm = wid >> 2, wn = wid & 3;
    const int rowBase = blockIdx.y * 128;
    const int colBase = blockIdx.x * 128;
    const int nc = K / BKC;
    const int frow = tid >> 2, fseg = tid & 3;

    auto fill = [&](int c) {
        const uint32_t sb = smem_u + (uint32_t)(c % NSTAGE) * (2 * TILE_BYTES);
        const uint32_t so = (uint32_t)(frow * PITCH + fseg * 8) * 2;
        cp16(sb + so, A + (size_t)(rowBase + frow) * lda + c * BKC + fseg * 8);
        cp16(sb + TILE_BYTES + so, B + (size_t)(colBase + frow) * ldb + c * BKC + fseg * 8);
        CP_COMMIT();
    };

    fill(0);
    fill(1);

    float acc[2][4][4];
    #pragma unroll
    for (int mt = 0; mt < 2; mt++)
        #pragma unroll
        for (int nt = 0; nt < 4; nt++)
            #pragma unroll
            for (int j = 0; j < 4; j++) acc[mt][nt][j] = 0.f;

    const int lr = lane & 15, lcq = (lane >> 4) << 3;

    for (int c = 0; c < nc; c++) {
        if (c + 2 < nc) fill(c + 2); else CP_COMMIT();
        CP_WAIT(2);
        __syncthreads();

        const uint32_t uA = smem_u + (uint32_t)(c % NSTAGE) * (2 * TILE_BYTES);
        const uint32_t uB = uA + TILE_BYTES;

        #pragma unroll
        for (int kk = 0; kk < 2; kk++) {
            const int kc = kk * 16;
            uint32_t a[2][4], bb[2][4];
            #pragma unroll
            for (int mt = 0; mt < 2; mt++) {
                const uint32_t off = (uint32_t)(((wm * 32 + mt * 16 + lr) * PITCH + kc + lcq) * 2);
                LDSM_X4(a[mt], uA + off);
            }
            #pragma unroll
            for (int p = 0; p < 2; p++) {
                const uint32_t off = (uint32_t)(((wn * 32 + p * 16 + lr) * PITCH + kc + lcq) * 2);
                LDSM_X4(bb[p], uB + off);
            }
            uint32_t bN[4][2] = {{bb[0][0], bb[0][2]}, {bb[0][1], bb[0][3]},
                                 {bb[1][0], bb[1][2]}, {bb[1][1], bb[1][3]}};
            #pragma unroll
            for (int mt = 0; mt < 2; mt++)
                #pragma unroll
                for (int nt = 0; nt < 4; nt++)
                    mma_f16(acc[mt][nt], a[mt], bN[nt]);
        }
    }

    #pragma unroll
    for (int mt = 0; mt < 2; mt++) {
        const int r0 = rowBase + wm * 32 + mt * 16 + g;
        #pragma unroll
        for (int nt = 0; nt < 4; nt++) {
            const int col = colBase + wn * 32 + nt * 8 + tq * 2;
            *(float2*)(C + (size_t)r0 * ldc + col)       = make_float2(acc[mt][nt][0], acc[mt][nt][1]);
            *(float2*)(C + (size_t)(r0 + 8) * ldc + col) = make_float2(acc[mt][nt][2], acc[mt][nt][3]);
        }
    }
}

// ---------------- scan phase A: per-block WY factors (round-12, correct) ---------
__global__ __launch_bounds__(512, 1) void scan_prep(
    const float* __restrict__ xi, const float* __restrict__ lam,
    const float* __restrict__ v)
{
    extern __shared__ float sa[];
    float* Gs  = sa;
    float* As  = Gs + RB * 65;
    float* Bs  = As + RB * PTCH;
    float* svs = Bs + RB * PTCH;

    const int blk = blockIdx.x;
    const int b = blk >> 5, n = blk & 31;
    const int t0 = n * 64 + 1;
    const int J = (n == 31) ? 63 : 64;
    const int tid = threadIdx.x;
    const int lane = tid & 31, wrp = tid >> 5;

    const float* lamb = lam + (size_t)b * TT * DI;
    const float* vb   = v   + (size_t)b * TT * DI;
    const float* xib  = xi  + (size_t)b * TT * DI;
    const size_t base = (size_t)blk * RB * DI;

    for (int r = wrp; r < RB; r += 16) {
        float s = 0.f;
        if (r < J) {
            const float4* vr = (const float4*)(vb + (size_t)(t0 + r) * DI);
            #pragma unroll
            for (int i = 0; i < 16; i++) {
                float4 a4 = vr[lane + i * 32];
                s += a4.x * a4.x + a4.y * a4.y + a4.z * a4.z + a4.w * a4.w;
            }
            #pragma unroll
            for (int o = 16; o; o >>= 1) s += __shfl_xor_sync(~0u, s, o);
        }
        if (lane == 0) svs[r] = (r < J) ? (2.0f / s) : 0.f;
    }
    __syncthreads();

    {
        const int c0 = tid * 4;
        float4 lp = make_float4(1.f, 1.f, 1.f, 1.f);
        float4 ip = make_float4(1.f, 1.f, 1.f, 1.f);
        float4 cu = make_float4(0.f, 0.f, 0.f, 0.f);
        for (int j = 0; j < J; j++) {
            const int t = t0 + j;
            const float4 la = *(const float4*)(lamb + (size_t)t * DI + c0);
            const float4 vv = *(const float4*)(vb   + (size_t)t * DI + c0);
            const float4 xx = *(const float4*)(xib  + (size_t)t * DI + c0);
            const float sj = svs[j];
            float4 vt, wh;
            vt.x = vv.x * lp.x; vt.y = vv.y * lp.y; vt.z = vv.z * lp.z; vt.w = vv.w * lp.w;
            wh.x = sj * vv.x * ip.x; wh.y = sj * vv.y * ip.y;
            wh.z = sj * vv.z * ip.z; wh.w = sj * vv.w * ip.w;
            lp.x *= la.x; lp.y *= la.y; lp.z *= la.z; lp.w *= la.w;
            ip.x *= __frcp_rn(la.x); ip.y *= __frcp_rn(la.y);
            ip.z *= __frcp_rn(la.z); ip.w *= __frcp_rn(la.w);
            cu.x += (1.f - la.x) * xx.x * ip.x;
            cu.y += (1.f - la.y) * xx.y * ip.y;
            cu.z += (1.f - la.z) * xx.z * ip.z;
            cu.w += (1.f - la.w) * xx.w * ip.w;
            const size_t o = base + (size_t)j * DI + c0;
            *(float4*)(g_Vt   + o) = vt;
            *(float4*)(g_Wh   + o) = wh;
            *(float4*)(g_Lam  + o) = lp;
            *(float4*)(g_CumU + o) = cu;
        }
        const float4 z4 = make_float4(0.f, 0.f, 0.f, 0.f);
        for (int j = J; j < RB; j++) {
            const size_t o = base + (size_t)j * DI + c0;
            *(float4*)(g_Vt + o) = z4;
            *(float4*)(g_Wh + o) = z4;
        }
    }
    __syncthreads();

    const int act  = (tid < 128);
    const int row0 = (tid >> 3) * 4;
    const int col0 = (tid & 7) * 8;
    {
        float acc[4][8];
        #pragma unroll
        for (int r = 0; r < 4; r++)
            #pragma unroll
            for (int e = 0; e < 8; e++) acc[r][e] = 0.f;

        for (int ch = 0; ch < DI; ch += 64) {
            for (int u = tid; u < 64 * 16; u += 512) {
                const int r = u >> 4, q = (u & 15) * 4;
                const float4 a4 = *(const float4*)(g_Vt + base + (size_t)r * DI + ch + q);
                *(float4*)(As + r * PTCH + q) = a4;
                const float4 b4 = *(const float4*)(g_Wh + base + (size_t)r * DI + ch + q);
                Bs[(q + 0) * PTCH + r] = b4.x;
                Bs[(q + 1) * PTCH + r] = b4.y;
                Bs[(q + 2) * PTCH + r] = b4.z;
                Bs[(q + 3) * PTCH + r] = b4.w;
            }
            __syncthreads();
            if (act) {
                #pragma unroll 4
                for (int k4 = 0; k4 < 16; k4++) {
                    float av[4][4];
                    #pragma unroll
                    for (int r = 0; r < 4; r++)
                        *(float4*)av[r] = *(const float4*)(As + (row0 + r) * PTCH + k4 * 4);
                    #pragma unroll
                    for (int kk = 0; kk < 4; kk++) {
                        const int k = k4 * 4 + kk;
                        float bv[8];
                        *(float4*)&bv[0] = *(const float4*)(Bs + k * PTCH + col0);
                        *(float4*)&bv[4] = *(const float4*)(Bs + k * PTCH + col0 + 4);
                        #pragma unroll
                        for (int r = 0; r < 4; r++)
                            #pragma unroll
                            for (int e = 0; e < 8; e++)
                                acc[r][e] += av[r][kk] * bv[e];
                    }
                }
            }
            __syncthreads();
        }
        if (act) {
            #pragma unroll
            for (int r = 0; r < 4; r++)
                #pragma unroll
                for (int e = 0; e < 8; e++) {
                    const int rr = row0 + r, cc = col0 + e;
                    Gs[rr * 65 + cc] = (cc < rr) ? acc[r][e] : 0.f;
                }
        }
    }

    for (int r = wrp; r < RB; r += 16) {
        float s = 0.f;
        if (r >= 1 && r < J) {
            const float4* a4p = (const float4*)(g_Vt + base + (size_t)r * DI);
            const float4* b4p = (const float4*)(g_CumU + base + (size_t)(r - 1) * DI);
            for (int i = lane; i < 512; i += 32) {
                const float4 a4 = a4p[i];
                const float4 b4 = b4p[i];
                s += a4.x * b4.x + a4.y * b4.y + a4.z * b4.z + a4.w * b4.w;
            }
            #pragma unroll
            for (int o = 16; o; o >>= 1) s += __shfl_xor_sync(~0u, s, o);
        }
        if (lane == 0) g_crow[blk * RB + r] = (r >= 1 && r < J) ? s : 0.f;
    }
    __syncthreads();

    for (int idx = tid; idx < RB * RB; idx += 512) {
        const int r = idx >> 6, c = idx & 63;
        const float gv = (c < r) ? Gs[r * 65 + c] : 0.f;
        As[r * PTCH + c] = -gv;
        Bs[r * PTCH + c] = (r == c) ? 1.f : 0.f;
    }
    __syncthreads();
    for (int m = 0; m < 6; m++) {
        {
            float t[4][8];
            #pragma unroll
            for (int r = 0; r < 4; r++)
                #pragma unroll
                for (int e = 0; e < 8; e++) t[r][e] = 0.f;
            if (act) {
                #pragma unroll 4
                for (int k4 = 0; k4 < 16; k4++) {
                    float av[4][4];
                    #pragma unroll
                    for (int r = 0; r < 4; r++)
                        *(float4*)av[r] = *(const float4*)(As + (row0 + r) * PTCH + k4 * 4);
                    #pragma unroll
                    for (int kk = 0; kk < 4; kk++) {
                        const int k = k4 * 4 + kk;
                        float bv[8];
                        *(float4*)&bv[0] = *(const float4*)(Bs + k * PTCH + col0);
                        *(float4*)&bv[4] = *(const float4*)(Bs + k * PTCH + col0 + 4);
                        #pragma unroll
                        for (int r = 0; r < 4; r++)
                            #pragma unroll
                            for (int e = 0; e < 8; e++)
                                t[r][e] += av[r][kk] * bv[e];
                    }
                }
            }
            __syncthreads();
            if (act) {
                #pragma unroll
                for (int r = 0; r < 4; r++) {
                    float4 s0 = *(const float4*)(Bs + (row0 + r) * PTCH + col0);
                    float4 s1 = *(const float4*)(Bs + (row0 + r) * PTCH + col0 + 4);
                    s0.x += t[r][0]; s0.y += t[r][1]; s0.z += t[r][2]; s0.w += t[r][3];
                    s1.x += t[r][4]; s1.y += t[r][5]; s1.z += t[r][6]; s1.w += t[r][7];
                    *(float4*)(Bs + (row0 + r) * PTCH + col0)     = s0;
                    *(float4*)(Bs + (row0 + r) * PTCH + col0 + 4) = s1;
                }
            }
            __syncthreads();
        }
        if (m < 5) {
            float t[4][8];
            #pragma unroll
            for (int r = 0; r < 4; r++)
                #pragma unroll
                for (int e = 0; e < 8; e++) t[r][e] = 0.f;
            if (act) {
                #pragma unroll 4
                for (int k4 = 0; k4 < 16; k4++) {
                    float av[4][4];
                    #pragma unroll
                    for (int r = 0; r < 4; r++)
                        *(float4*)av[r] = *(const float4*)(As + (row0 + r) * PTCH + k4 * 4);
                    #pragma unroll
                    for (int kk = 0; kk < 4; kk++) {
                        const int k = k4 * 4 + kk;
                        float bv[8];
                        *(float4*)&bv[0] = *(const float4*)(As + k * PTCH + col0);
                        *(float4*)&bv[4] = *(const float4*)(As + k * PTCH + col0 + 4);
                        #pragma unroll
                        for (int r = 0; r < 4; r++)
                            #pragma unroll
                            for (int e = 0; e < 8; e++)
                                t[r][e] += av[r][kk] * bv[e];
                    }
                }
            }
            __syncthreads();
            if (act) {
                #pragma unroll
                for (int r = 0; r < 4; r++) {
                    *(float4*)(As + (row0 + r) * PTCH + col0)     = *(float4*)&t[r][0];
                    *(float4*)(As + (row0 + r) * PTCH + col0 + 4) = *(float4*)&t[r][4];
                }
            }
            __syncthreads();
        }
    }
    for (int idx = tid; idx < RB * RB; idx += 512) {
        const int i = idx >> 6, j = idx & 63;
        g_MT[(size_t)blk * RB * RB + idx] = Bs[j * PTCH + i];
    }
}

// ---------------- scan phase B1: chain (sequential, 1 CTA/batch) -----------------
__global__ __launch_bounds__(1024, 1) void scan_chain(
    const float* __restrict__ xi, const float* __restrict__ sz,
    __half* __restrict__ gf)
{
    __shared__ float h0s[DI];
    __shared__ float MTs[RB * RB];
    __shared__ float fs[RB];
    __shared__ float as[RB];

    const int b = blockIdx.x;
    const int tid = threadIdx.x;
    const int lane = tid & 31, wrp = tid >> 5;
    const int c0 = tid * 2;

    const float* xib = xi + (size_t)b * TT * DI;
    const float* szb = sz + (size_t)b * TT * DI;
    __half* gfb = gf + (size_t)b * TT * DI;

    float2 h0 = *(const float2*)(xib + c0);
    {
        const float2 s0 = *(const float2*)(szb + c0);
        __half2 p = __floats2half2_rn(s0.x * h0.x, s0.y * h0.y);
        *(uint32_t*)(gfb + c0) = *(uint32_t*)&p;
        *(float2*)(h0s + c0) = h0;
    }
    __syncthreads();

    for (int n = 0; n < NBLK; n++) {
        const int blk = b * 32 + n;
        const int J = (n == 31) ? 63 : 64;
        const size_t base = (size_t)blk * RB * DI;

        for (int idx = tid; idx < RB * RB; idx += 1024)
            MTs[idx] = g_MT[(size_t)blk * RB * RB + idx];

        for (int r = wrp; r < RB; r += 32) {
            float s = 0.f;
            if (r < J) {
                const float4* a4p = (const float4*)(g_Vt + base + (size_t)r * DI);
                #pragma unroll
                for (int i = 0; i < 16; i++) {
                    const int ci = lane + i * 32;
                    const float4 a4 = a4p[ci];
                    const float4 h4 = *(const float4*)(h0s + ci * 4);
                    s += a4.x * h4.x + a4.y * h4.y + a4.z * h4.z + a4.w * h4.w;
                }
                #pragma unroll
                for (int o = 16; o; o >>= 1) s += __shfl_xor_sync(~0u, s, o);
            }
            if (lane == 0) fs[r] = s + g_crow[blk * RB + r];
        }
        __syncthreads();

        if (tid < RB) {
            float s = 0.f;
            #pragma unroll 8
            for (int i = 0; i < RB; i++)
                s += MTs[i * RB + tid] * fs[i];
            as[tid] = s;
            g_as[blk * RB + tid] = s;
        }
        __syncthreads();

        *(float2*)(g_h0e + (size_t)blk * DI + c0) = h0;

        float2 ws = make_float2(0.f, 0.f);
        #pragma unroll 8
        for (int j = 0; j < RB; j++) {
            const float2 wh = *(const float2*)(g_Wh + base + (size_t)j * DI + c0);
            const float aj = as[j];
            ws.x += wh.x * aj; ws.y += wh.y * aj;
        }
        const float2 la = *(const float2*)(g_Lam  + base + (size_t)(J - 1) * DI + c0);
        const float2 cu = *(const float2*)(g_CumU + base + (size_t)(J - 1) * DI + c0);
        h0.x = la.x * (h0.x + cu.x - ws.x);
        h0.y = la.y * (h0.y + cu.y - ws.y);
        *(float2*)(h0s + c0) = h0;
        __syncthreads();
    }
}

// ---------------- scan phase B2: reconstruction (parallel over 128 blocks) -------
__global__ __launch_bounds__(512, 1) void scan_recon(
    const float* __restrict__ sz, __half* __restrict__ gf)
{
    __shared__ float as[RB];
    const int blk = blockIdx.x;
    const int b = blk >> 5, n = blk & 31;
    const int t0 = n * 64 + 1;
    const int J = (n == 31) ? 63 : 64;
    const int tid = threadIdx.x;
    const int c0 = tid * 4;
    const size_t base = (size_t)blk * RB * DI;

    if (tid < RB) as[tid] = g_as[blk * RB + tid];
    __syncthreads();

    const float* szb = sz + (size_t)b * TT * DI;
    __half* gfb = gf + (size_t)b * TT * DI;

    const float4 h0 = *(const float4*)(g_h0e + (size_t)blk * DI + c0);
    float4 ws = make_float4(0.f, 0.f, 0.f, 0.f);

    for (int j = 0; j < J; j++) {
        const size_t o = base + (size_t)j * DI + c0;
        const float4 wh = *(const float4*)(g_Wh + o);
        const float4 cu = *(const float4*)(g_CumU + o);
        const float4 la = *(const float4*)(g_Lam + o);
        const float4 s4 = *(const float4*)(szb + (size_t)(t0 + j) * DI + c0);
        const float aj = as[j];
        ws.x += wh.x * aj; ws.y += wh.y * aj;
        ws.z += wh.z * aj; ws.w += wh.w * aj;
        float4 hj;
        hj.x = la.x * (h0.x + cu.x - ws.x);
        hj.y = la.y * (h0.y + cu.y - ws.y);
        hj.z = la.z * (h0.z + cu.z - ws.z);
        hj.w = la.w * (h0.w + cu.w - ws.w);
        __half2 p0 = __floats2half2_rn(s4.x * hj.x, s4.y * hj.y);
        __half2 p1 = __floats2half2_rn(s4.z * hj.z, s4.w * hj.w);
        *(uint2*)(gfb + (size_t)(t0 + j) * DI + c0) =
            make_uint2(*(uint32_t*)&p0, *(uint32_t*)&p1);
    }
}

// ---------------- launcher ----------------------------------------------------------
extern "C" void kernel_launch(void* const* d_in, const int* in_sizes, int n_in,
                              void* d_out, int out_size)
{
    const float* x     = (const float*)d_in[0];
    const float* omega = (const float*)d_in[1];
    const float* Win   = (const float*)d_in[2];
    const float* Wl    = (const float*)d_in[3];
    const float* bl    = (const float*)d_in[4];
    const float* Wv    = (const float*)d_in[5];
    const float* bv    = (const float*)d_in[6];
    const float* Wout  = (const float*)d_in[7];
    float* out = (float*)d_out;

    __nv_bfloat16 *xh, *xl, *winh, *winl, *wlh, *wll, *wvh, *wvl;
    __nv_bfloat16 *xih, *xil;
    __half *wof, *gfp;
    float *xi, *szp, *lam, *v, *fcol;
    cudaGetSymbolAddress((void**)&xh,   g_xh);   cudaGetSymbolAddress((void**)&xl,   g_xl);
    cudaGetSymbolAddress((void**)&winh, g_winh); cudaGetSymbolAddress((void**)&winl, g_winl);
    cudaGetSymbolAddress((void**)&wlh,  g_wlh);  cudaGetSymbolAddress((void**)&wll,  g_wll);
    cudaGetSymbolAddress((void**)&wvh,  g_wvh);  cudaGetSymbolAddress((void**)&wvl,  g_wvl);
    cudaGetSymbolAddress((void**)&wof,  g_wof);
    cudaGetSymbolAddress((void**)&xi,   g_xi);
    cudaGetSymbolAddress((void**)&xih,  g_xih);  cudaGetSymbolAddress((void**)&xil,  g_xil);
    cudaGetSymbolAddress((void**)&szp,  g_sz);
    cudaGetSymbolAddress((void**)&lam,  g_lam);  cudaGetSymbolAddress((void**)&v,    g_v);
    cudaGetSymbolAddress((void**)&gfp,  g_gf);
    cudaGetSymbolAddress((void**)&fcol, g_fcolA);

    cudaFuncSetAttribute(gemm_ps, cudaFuncAttributeMaxDynamicSharedMemorySize, GEMM_SMEM);
    cudaFuncSetAttribute(gemm_f16, cudaFuncAttributeMaxDynamicSharedMemorySize, F16_SMEM);
    cudaFuncSetAttribute(scan_prep, cudaFuncAttributeMaxDynamicSharedMemorySize, SMEMA);

    // 0) splits (seg4 = Wout -> fp16)
    mega_pre<<<dim3((MROWS * DM) / 1024, 5), 256>>>(
        x, xh, xl, Win, winh, winl, Wl, wlh, wll, Wv, wvh, wvl, Wout, wof);

    // 1) GEMM1: xz -> xi (fp32 + split) | silu(z)   [3-term bf16]
    gemm_ps<<<dim3(DX / 128, MROWS / 128, 1), GT, GEMM_SMEM>>>(
        xh, xl, DM, winh, winl, nullptr, nullptr, DM, DM,
        xi, nullptr, DI, nullptr, nullptr, fcol, xih, xil, szp, 2, 2, 3, 3);

    // 2) fcol
    fcol_kernel<<<DI / 256, 256>>>(omega, fcol);

    // 3) GEMM2+3 fused: z=0 -> lam [2-term], z=1 -> v [3-term]
    gemm_ps<<<dim3(DI / 128, MROWS / 128, 2), GT, GEMM_SMEM>>>(
        xih, xil, DI, wlh, wll, wvh, wvl, DI, DI,
        lam, v, DI, bl, bv, fcol, nullptr, nullptr, nullptr, 1, 0, 2, 3);

    // 4) scan prep
    scan_prep<<<TOTBLK, 512, SMEMA>>>(xi, lam, v);

    // 5) chain (sequential over blocks)
    scan_chain<<<BB, 1024>>>(xi, szp, gfp);

    // 6) reconstruction (parallel over 128 blocks)
    scan_recon<<<TOTBLK, 512>>>(szp, gfp);

    // 7) GEMM4: out = g @ Wout^T   [plain fp16, 1-term]
    gemm_f16<<<dim3(DM / 128, MROWS / 128), GT, F16_SMEM>>>(
        gfp, DI, wof, DI, DI, out, DM);
}

// round 17
// speedup vs baseline: 1.2586x; 1.1580x over previous
#include <cuda_runtime.h>
#include <cuda_bf16.h>
#include <cuda_fp16.h>
#include <cstdint>
#include <cstddef>

// Problem constants
#define BB   4
#define TT   2048
#define DM   1024
#define DI   2048
#define DX   4096
#define MROWS (BB*TT)   // 8192

// GEMM tiling (128x128 CTA, 16 warps of 32x32)
#define BKC   32
#define PITCH 40
#define TILE_BYTES (128*PITCH*2)
#define STAGE_BYTES (4*TILE_BYTES)
#define NSTAGE 4
#define GEMM_SMEM (NSTAGE*STAGE_BYTES + 1024)
#define F16_SMEM  (NSTAGE*2*TILE_BYTES + 1024)
#define GT    512

// Block-scan config
#define RB    64
#define NBLK  32
#define TOTBLK 128
#define PTCH  68
#define SMEMA ((RB*65 + 2*RB*PTCH + RB)*4)

// ---------------- scratch ----------------------------------------------------
__device__ __nv_bfloat16 g_xh [(size_t)MROWS * DM],  g_xl [(size_t)MROWS * DM];
__device__ __half        g_xf [(size_t)MROWS * DM];
__device__ __nv_bfloat16 g_winh[(size_t)DI * DM],    g_winl[(size_t)DI * DM];
__device__ __half        g_wzf[(size_t)DI * DM];     // Win z-half rows, fp16
__device__ __half        g_wlf[(size_t)DI * DI];
__device__ __nv_bfloat16 g_wvh[(size_t)DI * DI],     g_wvl[(size_t)DI * DI];
__device__ __half        g_wof[(size_t)DM * DI];
__device__ float         g_xi [(size_t)MROWS * DI];
__device__ __nv_bfloat16 g_xih[(size_t)MROWS * DI],  g_xil[(size_t)MROWS * DI];
__device__ __half        g_xif[(size_t)MROWS * DI];
__device__ float         g_sz [(size_t)MROWS * DI];
__device__ float         g_lam[(size_t)MROWS * DI];
__device__ float         g_v  [(size_t)MROWS * DI];
__device__ __half        g_gf [(size_t)MROWS * DI];
__device__ float         g_fcolA[DI];
// block-scan scratch
__device__ float g_Lam [(size_t)TOTBLK * RB * DI];
__device__ float g_Vt  [(size_t)TOTBLK * RB * DI];
__device__ float g_Wh  [(size_t)TOTBLK * RB * DI];
__device__ float g_CumU[(size_t)TOTBLK * RB * DI];
__device__ float g_MT  [(size_t)TOTBLK * RB * RB];
__device__ float g_crow[(size_t)TOTBLK * RB];
__device__ float g_h0e [(size_t)TOTBLK * DI];
__device__ float g_as  [(size_t)TOTBLK * RB];

// ---------------- helpers ------------------------------------------------------
__device__ __forceinline__ uint32_t smem_u32(const void* p) {
    uint32_t a;
    asm("{ .reg .u64 t; cvta.to.shared.u64 t, %1; cvt.u32.u64 %0, t; }" : "=r"(a) : "l"(p));
    return a;
}
__device__ __forceinline__ void cp16(uint32_t dst, const void* src) {
    asm volatile("cp.async.cg.shared.global [%0], [%1], 16;" :: "r"(dst), "l"(src));
}
#define CP_COMMIT() asm volatile("cp.async.commit_group;" ::: "memory")
#define CP_WAIT(n)  asm volatile("cp.async.wait_group %0;" :: "n"(n) : "memory")

__device__ __forceinline__ void mma_bf16(float* c, const uint32_t* a, const uint32_t* b) {
    asm volatile(
        "mma.sync.aligned.m16n8k16.row.col.f32.bf16.bf16.f32 "
        "{%0,%1,%2,%3}, {%4,%5,%6,%7}, {%8,%9}, {%0,%1,%2,%3};"
        : "+f"(c[0]), "+f"(c[1]), "+f"(c[2]), "+f"(c[3])
        : "r"(a[0]), "r"(a[1]), "r"(a[2]), "r"(a[3]), "r"(b[0]), "r"(b[1]));
}
__device__ __forceinline__ void mma_f16(float* c, const uint32_t* a, const uint32_t* b) {
    asm volatile(
        "mma.sync.aligned.m16n8k16.row.col.f32.f16.f16.f32 "
        "{%0,%1,%2,%3}, {%4,%5,%6,%7}, {%8,%9}, {%0,%1,%2,%3};"
        : "+f"(c[0]), "+f"(c[1]), "+f"(c[2]), "+f"(c[3])
        : "r"(a[0]), "r"(a[1]), "r"(a[2]), "r"(a[3]), "r"(b[0]), "r"(b[1]));
}
#define LDSM_X4(r, addr) \
    asm volatile("ldmatrix.sync.aligned.m8n8.x4.shared.b16 {%0,%1,%2,%3}, [%4];" \
        : "=r"((r)[0]), "=r"((r)[1]), "=r"((r)[2]), "=r"((r)[3]) : "r"(addr))

__device__ __forceinline__ void split2(float a, float b, uint32_t& hv, uint32_t& lv) {
    __nv_bfloat162 h = __float22bfloat162_rn(make_float2(a, b));
    float2 hf = __bfloat1622float2(h);
    __nv_bfloat162 l = __float22bfloat162_rn(make_float2(a - hf.x, b - hf.y));
    hv = *(uint32_t*)&h; lv = *(uint32_t*)&l;
}

// ---------------- mega pre-pass ---------------------------------------------------
// segs: 0 x->split, 1 x->f16, 2 Win[0:DI)->split, 3 Win[DI:DX)->f16,
//       4 Wl->f16, 5 Wv->split, 6 Wout->f16
__global__ __launch_bounds__(256) void mega_pre(
    const float* __restrict__ x, const float* __restrict__ Win,
    const float* __restrict__ Wl, const float* __restrict__ Wv,
    const float* __restrict__ Wout)
{
    const int seg = blockIdx.y;
    const int i = (blockIdx.x * 256 + threadIdx.x) * 4;

    if (seg == 1 || seg == 3 || seg == 4 || seg == 6) {
        const float* src; __half* dst; int n;
        switch (seg) {
            case 1: src = x;              dst = g_xf;  n = MROWS * DM; break;
            case 3: src = Win + (size_t)DI * DM; dst = g_wzf; n = DI * DM; break;
            case 4: src = Wl;             dst = g_wlf; n = DI * DI;    break;
            default:src = Wout;           dst = g_wof; n = DM * DI;    break;
        }
        if (i >= n) return;
        float4 f = *(const float4*)(src + i);
        __half2 p0 = __floats2half2_rn(f.x, f.y);
        __half2 p1 = __floats2half2_rn(f.z, f.w);
        *(uint2*)(dst + i) = make_uint2(*(uint32_t*)&p0, *(uint32_t*)&p1);
        return;
    }
    const float* src; __nv_bfloat16 *hi, *lo; int n;
    switch (seg) {
        case 0: src = x;   hi = g_xh;   lo = g_xl;   n = MROWS * DM; break;
        case 2: src = Win; hi = g_winh; lo = g_winl; n = DI * DM;    break;
        default:src = Wv;  hi = g_wvh;  lo = g_wvl;  n = DI * DI;    break;
    }
    if (i >= n) return;
    float4 f = *(const float4*)(src + i);
    uint32_t h0, l0, h1, l1;
    split2(f.x, f.y, h0, l0);
    split2(f.z, f.w, h1, l1);
    *(uint2*)(hi + i) = make_uint2(h0, h1);
    *(uint2*)(lo + i) = make_uint2(l0, l1);
}

__global__ void fcol_kernel(const float* __restrict__ omega, float* __restrict__ fcol) {
    int i = blockIdx.x * 256 + threadIdx.x;
    if (i < DI) fcol[i] = -8.0f * log1pf(__expf(omega[i]));
}

// ---------------- bf16 split NT GEMM (512 thr, 16 warps 32x32) --------------------
// mode 0: C = acc + bias ; mode 2: C=acc fp32 + split->Chi/Clo + fp16->Cf
__global__ __launch_bounds__(GT, 1) void gemm_ps(
    const __nv_bfloat16* __restrict__ Ahg, const __nv_bfloat16* __restrict__ Alg, int lda,
    const __nv_bfloat16* __restrict__ Bhg, const __nv_bfloat16* __restrict__ Blg, int ldb,
    int K,
    float* __restrict__ C0, int ldc,
    const float* __restrict__ bias,
    __nv_bfloat16* __restrict__ Chi, __nv_bfloat16* __restrict__ Clo,
    __half* __restrict__ Cf, int mode)
{
    extern __shared__ char smraw[];
    const uint32_t smem_u = smem_u32(smraw);
    float* bias_s = (float*)(smraw + NSTAGE * STAGE_BYTES);

    const int tid = threadIdx.x;
    const int wid = tid >> 5, lane = tid & 31;
    const int g = lane >> 2, tq = lane & 3;
    const int wm = wid >> 2, wn = wid & 3;
    const int rowBase = blockIdx.y * 128;
    const int colBase = blockIdx.x * 128;

    if (tid < 128) {
        int c = colBase + tid;
        bias_s[tid] = bias ? bias[c] : 0.f;
    }

    const int nc = K / BKC;
    const int frow = tid >> 2, fseg = tid & 3;
    auto fill = [&](int c) {
        const uint32_t sb = smem_u + (uint32_t)(c % NSTAGE) * STAGE_BYTES;
        const uint32_t so = (uint32_t)(frow * PITCH + fseg * 8) * 2;
        const size_t ga = (size_t)(rowBase + frow) * lda + c * BKC + fseg * 8;
        const size_t gb = (size_t)(colBase + frow) * ldb + c * BKC + fseg * 8;
        cp16(sb + 0 * TILE_BYTES + so, Ahg + ga);
        cp16(sb + 1 * TILE_BYTES + so, Alg + ga);
        cp16(sb + 2 * TILE_BYTES + so, Bhg + gb);
        cp16(sb + 3 * TILE_BYTES + so, Blg + gb);
        CP_COMMIT();
    };

    fill(0);
    fill(1);

    float acc[2][4][4];
    #pragma unroll
    for (int mt = 0; mt < 2; mt++)
        #pragma unroll
        for (int nt = 0; nt < 4; nt++)
            #pragma unroll
            for (int j = 0; j < 4; j++) acc[mt][nt][j] = 0.f;

    const int lr = lane & 15, lcq = (lane >> 4) << 3;

    for (int c = 0; c < nc; c++) {
        if (c + 2 < nc) fill(c + 2); else CP_COMMIT();
        CP_WAIT(2);
        __syncthreads();

        const uint32_t ub = smem_u + (uint32_t)(c % NSTAGE) * STAGE_BYTES;
        const uint32_t uAh = ub, uAl = ub + TILE_BYTES;
        const uint32_t uBh = ub + 2 * TILE_BYTES, uBl = ub + 3 * TILE_BYTES;

        #pragma unroll
        for (int kk = 0; kk < 2; kk++) {
            const int kc = kk * 16;
            uint32_t ah[2][4], al[2][4], bh[2][4], bl[2][4];
            #pragma unroll
            for (int mt = 0; mt < 2; mt++) {
                const uint32_t off = (uint32_t)(((wm * 32 + mt * 16 + lr) * PITCH + kc + lcq) * 2);
                LDSM_X4(ah[mt], uAh + off);
            }
            #pragma unroll
            for (int p = 0; p < 2; p++) {
                const uint32_t off = (uint32_t)(((wn * 32 + p * 16 + lr) * PITCH + kc + lcq) * 2);
                LDSM_X4(bh[p], uBh + off);
                LDSM_X4(bl[p], uBl + off);
            }
            uint32_t bH[4][2] = {{bh[0][0], bh[0][2]}, {bh[0][1], bh[0][3]},
                                 {bh[1][0], bh[1][2]}, {bh[1][1], bh[1][3]}};
            uint32_t bL[4][2] = {{bl[0][0], bl[0][2]}, {bl[0][1], bl[0][3]},
                                 {bl[1][0], bl[1][2]}, {bl[1][1], bl[1][3]}};
            #pragma unroll
            for (int mt = 0; mt < 2; mt++)
                #pragma unroll
                for (int nt = 0; nt < 4; nt++)
                    mma_bf16(acc[mt][nt], ah[mt], bH[nt]);
            #pragma unroll
            for (int mt = 0; mt < 2; mt++)
                #pragma unroll
                for (int nt = 0; nt < 4; nt++)
                    mma_bf16(acc[mt][nt], ah[mt], bL[nt]);
            #pragma unroll
            for (int mt = 0; mt < 2; mt++) {
                const uint32_t off = (uint32_t)(((wm * 32 + mt * 16 + lr) * PITCH + kc + lcq) * 2);
                LDSM_X4(al[mt], uAl + off);
            }
            #pragma unroll
            for (int mt = 0; mt < 2; mt++)
                #pragma unroll
                for (int nt = 0; nt < 4; nt++)
                    mma_bf16(acc[mt][nt], al[mt], bH[nt]);
        }
    }

    #pragma unroll
    for (int mt = 0; mt < 2; mt++) {
        const int r0 = rowBase + wm * 32 + mt * 16 + g;
        #pragma unroll
        for (int nt = 0; nt < 4; nt++) {
            const int col = wn * 32 + nt * 8 + tq * 2;
            const int cc = colBase + col;
            float v0 = acc[mt][nt][0] + bias_s[col];
            float v1 = acc[mt][nt][1] + bias_s[col + 1];
            float v2 = acc[mt][nt][2] + bias_s[col];
            float v3 = acc[mt][nt][3] + bias_s[col + 1];
            *(float2*)(C0 + (size_t)r0 * ldc + cc)       = make_float2(v0, v1);
            *(float2*)(C0 + (size_t)(r0 + 8) * ldc + cc) = make_float2(v2, v3);
            if (mode == 2) {
                uint32_t h0, l0, h1, l1;
                split2(v0, v1, h0, l0);
                split2(v2, v3, h1, l1);
                *(uint32_t*)(Chi + (size_t)r0 * DI + cc)       = h0;
                *(uint32_t*)(Clo + (size_t)r0 * DI + cc)       = l0;
                *(uint32_t*)(Chi + (size_t)(r0 + 8) * DI + cc) = h1;
                *(uint32_t*)(Clo + (size_t)(r0 + 8) * DI + cc) = l1;
                __half2 p0 = __floats2half2_rn(v0, v1);
                __half2 p1 = __floats2half2_rn(v2, v3);
                *(uint32_t*)(Cf + (size_t)r0 * DI + cc)       = *(uint32_t*)&p0;
                *(uint32_t*)(Cf + (size_t)(r0 + 8) * DI + cc) = *(uint32_t*)&p1;
            }
        }
    }
}

// ---------------- fp16 NT GEMM, dual-z, modal epilogue -----------------------------
// mode 0: C = acc ; mode 1: C = exp(fcol*sigmoid(acc+bias)) ; mode 3: C = silu(acc)
__global__ __launch_bounds__(GT, 1) void gemm_f16(
    const __half* __restrict__ A0, int lda0,
    const __half* __restrict__ B0, int ldb0, int K0,
    const __half* __restrict__ A1, int lda1,
    const __half* __restrict__ B1, int ldb1, int K1,
    float* __restrict__ C0, int ldc0, float* __restrict__ C1, int ldc1,
    const float* __restrict__ bias0, const float* __restrict__ bias1,
    const float* __restrict__ fcolg, int mode0, int mode1)
{
    extern __shared__ char smraw[];
    const uint32_t smem_u = smem_u32(smraw);
    float* bias_s = (float*)(smraw + NSTAGE * 2 * TILE_BYTES);
    float* fcol_s = bias_s + 128;

    const int tid = threadIdx.x;
    const int wid = tid >> 5, lane = tid & 31;
    const int g = lane >> 2, tq = lane & 3;
    const int wm = wid >> 2, wn = wid & 3;
    const int rowBase = blockIdx.y * 128;
    const int colBase = blockIdx.x * 128;

    const __half* A = A0; const __half* B = B0;
    int lda = lda0, ldb = ldb0, K = K0, md = mode0, ldc = ldc0;
    float* C = C0; const float* biasp = bias0;
    if (blockIdx.z == 1) {
        A = A1; B = B1; lda = lda1; ldb = ldb1; K = K1;
        md = mode1; C = C1; ldc = ldc1; biasp = bias1;
    }

    if (tid < 128) {
        int c = colBase + tid;
        bias_s[tid] = biasp ? biasp[c] : 0.f;
        fcol_s[tid] = (md == 1) ? fcolg[c] : 0.f;
    }

    const int nc = K / BKC;
    const int frow = tid >> 2, fseg = tid & 3;

    auto fill = [&](int c) {
        const uint32_t sb = smem_u + (uint32_t)(c % NSTAGE) * (2 * TILE_BYTES);
        const uint32_t so = (uint32_t)(frow * PITCH + fseg * 8) * 2;
        cp16(sb + so, A + (size_t)(rowBase + frow) * lda + c * BKC + fseg * 8);
        cp16(sb + TILE_BYTES + so, B + (size_t)(colBase + frow) * ldb + c * BKC + fseg * 8);
        CP_COMMIT();
    };

    fill(0);
    fill(1);

    float acc[2][4][4];
    #pragma unroll
    for (int mt = 0; mt < 2; mt++)
        #pragma unroll
        for (int nt = 0; nt < 4; nt++)
            #pragma unroll
            for (int j = 0; j < 4; j++) acc[mt][nt][j] = 0.f;

    const int lr = lane & 15, lcq = (lane >> 4) << 3;

    for (int c = 0; c < nc; c++) {
        if (c + 2 < nc) fill(c + 2); else CP_COMMIT();
        CP_WAIT(2);
        __syncthreads();

        const uint32_t uA = smem_u + (uint32_t)(c % NSTAGE) * (2 * TILE_BYTES);
        const uint32_t uB = uA + TILE_BYTES;

        #pragma unroll
        for (int kk = 0; kk < 2; kk++) {
            const int kc = kk * 16;
            uint32_t a[2][4], bb[2][4];
            #pragma unroll
            for (int mt = 0; mt < 2; mt++) {
                const uint32_t off = (uint32_t)(((wm * 32 + mt * 16 + lr) * PITCH + kc + lcq) * 2);
                LDSM_X4(a[mt], uA + off);
            }
            #pragma unroll
            for (int p = 0; p < 2; p++) {
                const uint32_t off = (uint32_t)(((wn * 32 + p * 16 + lr) * PITCH + kc + lcq) * 2);
                LDSM_X4(bb[p], uB + off);
            }
            uint32_t bN[4][2] = {{bb[0][0], bb[0][2]}, {bb[0][1], bb[0][3]},
                                 {bb[1][0], bb[1][2]}, {bb[1][1], bb[1][3]}};
            #pragma unroll
            for (int mt = 0; mt < 2; mt++)
                #pragma unroll
                for (int nt = 0; nt < 4; nt++)
                    mma_f16(acc[mt][nt], a[mt], bN[nt]);
        }
    }

    #pragma unroll
    for (int mt = 0; mt < 2; mt++) {
        const int r0 = rowBase + wm * 32 + mt * 16 + g;
        #pragma unroll
        for (int nt = 0; nt < 4; nt++) {
            const int col = wn * 32 + nt * 8 + tq * 2;
            float v0 = acc[mt][nt][0] + bias_s[col];
            float v1 = acc[mt][nt][1] + bias_s[col + 1];
            float v2 = acc[mt][nt][2] + bias_s[col];
            float v3 = acc[mt][nt][3] + bias_s[col + 1];
            if (md == 1) {
                const float f0 = fcol_s[col], f1 = fcol_s[col + 1];
                v0 = __expf(f0 * __frcp_rn(1.0f + __expf(-v0)));
                v1 = __expf(f1 * __frcp_rn(1.0f + __expf(-v1)));
                v2 = __expf(f0 * __frcp_rn(1.0f + __expf(-v2)));
                v3 = __expf(f1 * __frcp_rn(1.0f + __expf(-v3)));
            } else if (md == 3) {
                v0 = v0 * __frcp_rn(1.0f + __expf(-v0));
                v1 = v1 * __frcp_rn(1.0f + __expf(-v1));
                v2 = v2 * __frcp_rn(1.0f + __expf(-v2));
                v3 = v3 * __frcp_rn(1.0f + __expf(-v3));
            }
            const int cc = colBase + col;
            *(float2*)(C + (size_t)r0 * ldc + cc)       = make_float2(v0, v1);
            *(float2*)(C + (size_t)(r0 + 8) * ldc + cc) = make_float2(v2, v3);
        }
    }
}

// ---------------- scan phase A: per-block WY factors (round-12, correct) ---------
__global__ __launch_bounds__(512, 1) void scan_prep(
    const float* __restrict__ xi, const float* __restrict__ lam,
    const float* __restrict__ v)
{
    extern __shared__ float sa[];
    float* Gs  = sa;
    float* As  = Gs + RB * 65;
    float* Bs  = As + RB * PTCH;
    float* svs = Bs + RB * PTCH;

    const int blk = blockIdx.x;
    const int b = blk >> 5, n = blk & 31;
    const int t0 = n * 64 + 1;
    const int J = (n == 31) ? 63 : 64;
    const int tid = threadIdx.x;
    const int lane = tid & 31, wrp = tid >> 5;

    const float* lamb = lam + (size_t)b * TT * DI;
    const float* vb   = v   + (size_t)b * TT * DI;
    const float* xib  = xi  + (size_t)b * TT * DI;
    const size_t base = (size_t)blk * RB * DI;

    for (int r = wrp; r < RB; r += 16) {
        float s = 0.f;
        if (r < J) {
            const float4* vr = (const float4*)(vb + (size_t)(t0 + r) * DI);
            #pragma unroll
            for (int i = 0; i < 16; i++) {
                float4 a4 = vr[lane + i * 32];
                s += a4.x * a4.x + a4.y * a4.y + a4.z * a4.z + a4.w * a4.w;
            }
            #pragma unroll
            for (int o = 16; o; o >>= 1) s += __shfl_xor_sync(~0u, s, o);
        }
        if (lane == 0) svs[r] = (r < J) ? (2.0f / s) : 0.f;
    }
    __syncthreads();

    {
        const int c0 = tid * 4;
        float4 lp = make_float4(1.f, 1.f, 1.f, 1.f);
        float4 ip = make_float4(1.f, 1.f, 1.f, 1.f);
        float4 cu = make_float4(0.f, 0.f, 0.f, 0.f);
        for (int j = 0; j < J; j++) {
            const int t = t0 + j;
            const float4 la = *(const float4*)(lamb + (size_t)t * DI + c0);
            const float4 vv = *(const float4*)(vb   + (size_t)t * DI + c0);
            const float4 xx = *(const float4*)(xib  + (size_t)t * DI + c0);
            const float sj = svs[j];
            float4 vt, wh;
            vt.x = vv.x * lp.x; vt.y = vv.y * lp.y; vt.z = vv.z * lp.z; vt.w = vv.w * lp.w;
            wh.x = sj * vv.x * ip.x; wh.y = sj * vv.y * ip.y;
            wh.z = sj * vv.z * ip.z; wh.w = sj * vv.w * ip.w;
            lp.x *= la.x; lp.y *= la.y; lp.z *= la.z; lp.w *= la.w;
            ip.x *= __frcp_rn(la.x); ip.y *= __frcp_rn(la.y);
            ip.z *= __frcp_rn(la.z); ip.w *= __frcp_rn(la.w);
            cu.x += (1.f - la.x) * xx.x * ip.x;
            cu.y += (1.f - la.y) * xx.y * ip.y;
            cu.z += (1.f - la.z) * xx.z * ip.z;
            cu.w += (1.f - la.w) * xx.w * ip.w;
            const size_t o = base + (size_t)j * DI + c0;
            *(float4*)(g_Vt   + o) = vt;
            *(float4*)(g_Wh   + o) = wh;
            *(float4*)(g_Lam  + o) = lp;
            *(float4*)(g_CumU + o) = cu;
        }
        const float4 z4 = make_float4(0.f, 0.f, 0.f, 0.f);
        for (int j = J; j < RB; j++) {
            const size_t o = base + (size_t)j * DI + c0;
            *(float4*)(g_Vt + o) = z4;
            *(float4*)(g_Wh + o) = z4;
        }
    }
    __syncthreads();

    const int act  = (tid < 128);
    const int row0 = (tid >> 3) * 4;
    const int col0 = (tid & 7) * 8;
    {
        float acc[4][8];
        #pragma unroll
        for (int r = 0; r < 4; r++)
            #pragma unroll
            for (int e = 0; e < 8; e++) acc[r][e] = 0.f;

        for (int ch = 0; ch < DI; ch += 64) {
            for (int u = tid; u < 64 * 16; u += 512) {
                const int r = u >> 4, q = (u & 15) * 4;
                const float4 a4 = *(const float4*)(g_Vt + base + (size_t)r * DI + ch + q);
                *(float4*)(As + r * PTCH + q) = a4;
                const float4 b4 = *(const float4*)(g_Wh + base + (size_t)r * DI + ch + q);
                Bs[(q + 0) * PTCH + r] = b4.x;
                Bs[(q + 1) * PTCH + r] = b4.y;
                Bs[(q + 2) * PTCH + r] = b4.z;
                Bs[(q + 3) * PTCH + r] = b4.w;
            }
            __syncthreads();
            if (act) {
                #pragma unroll 4
                for (int k4 = 0; k4 < 16; k4++) {
                    float av[4][4];
                    #pragma unroll
                    for (int r = 0; r < 4; r++)
                        *(float4*)av[r] = *(const float4*)(As + (row0 + r) * PTCH + k4 * 4);
                    #pragma unroll
                    for (int kk = 0; kk < 4; kk++) {
                        const int k = k4 * 4 + kk;
                        float bv[8];
                        *(float4*)&bv[0] = *(const float4*)(Bs + k * PTCH + col0);
                        *(float4*)&bv[4] = *(const float4*)(Bs + k * PTCH + col0 + 4);
                        #pragma unroll
                        for (int r = 0; r < 4; r++)
                            #pragma unroll
                            for (int e = 0; e < 8; e++)
                                acc[r][e] += av[r][kk] * bv[e];
                    }
                }
            }
            __syncthreads();
        }
        if (act) {
            #pragma unroll
            for (int r = 0; r < 4; r++)
                #pragma unroll
                for (int e = 0; e < 8; e++) {
                    const int rr = row0 + r, cc = col0 + e;
                    Gs[rr * 65 + cc] = (cc < rr) ? acc[r][e] : 0.f;
                }
        }
    }

    for (int r = wrp; r < RB; r += 16) {
        float s = 0.f;
        if (r >= 1 && r < J) {
            const float4* a4p = (const float4*)(g_Vt + base + (size_t)r * DI);
            const float4* b4p = (const float4*)(g_CumU + base + (size_t)(r - 1) * DI);
            for (int i = lane; i < 512; i += 32) {
                const float4 a4 = a4p[i];
                const float4 b4 = b4p[i];
                s += a4.x * b4.x + a4.y * b4.y + a4.z * b4.z + a4.w * b4.w;
            }
            #pragma unroll
            for (int o = 16; o; o >>= 1) s += __shfl_xor_sync(~0u, s, o);
        }
        if (lane == 0) g_crow[blk * RB + r] = (r >= 1 && r < J) ? s : 0.f;
    }
    __syncthreads();

    for (int idx = tid; idx < RB * RB; idx += 512) {
        const int r = idx >> 6, c = idx & 63;
        const float gv = (c < r) ? Gs[r * 65 + c] : 0.f;
        As[r * PTCH + c] = -gv;
        Bs[r * PTCH + c] = (r == c) ? 1.f : 0.f;
    }
    __syncthreads();
    for (int m = 0; m < 6; m++) {
        {
            float t[4][8];
            #pragma unroll
            for (int r = 0; r < 4; r++)
                #pragma unroll
                for (int e = 0; e < 8; e++) t[r][e] = 0.f;
            if (act) {
                #pragma unroll 4
                for (int k4 = 0; k4 < 16; k4++) {
                    float av[4][4];
                    #pragma unroll
                    for (int r = 0; r < 4; r++)
                        *(float4*)av[r] = *(const float4*)(As + (row0 + r) * PTCH + k4 * 4);
                    #pragma unroll
                    for (int kk = 0; kk < 4; kk++) {
                        const int k = k4 * 4 + kk;
                        float bv[8];
                        *(float4*)&bv[0] = *(const float4*)(Bs + k * PTCH + col0);
                        *(float4*)&bv[4] = *(const float4*)(Bs + k * PTCH + col0 + 4);
                        #pragma unroll
                        for (int r = 0; r < 4; r++)
                            #pragma unroll
                            for (int e = 0; e < 8; e++)
                                t[r][e] += av[r][kk] * bv[e];
                    }
                }
            }
            __syncthreads();
            if (act) {
                #pragma unroll
                for (int r = 0; r < 4; r++) {
                    float4 s0 = *(const float4*)(Bs + (row0 + r) * PTCH + col0);
                    float4 s1 = *(const float4*)(Bs + (row0 + r) * PTCH + col0 + 4);
                    s0.x += t[r][0]; s0.y += t[r][1]; s0.z += t[r][2]; s0.w += t[r][3];
                    s1.x += t[r][4]; s1.y += t[r][5]; s1.z += t[r][6]; s1.w += t[r][7];
                    *(float4*)(Bs + (row0 + r) * PTCH + col0)     = s0;
                    *(float4*)(Bs + (row0 + r) * PTCH + col0 + 4) = s1;
                }
            }
            __syncthreads();
        }
        if (m < 5) {
            float t[4][8];
            #pragma unroll
            for (int r = 0; r < 4; r++)
                #pragma unroll
                for (int e = 0; e < 8; e++) t[r][e] = 0.f;
            if (act) {
                #pragma unroll 4
                for (int k4 = 0; k4 < 16; k4++) {
                    float av[4][4];
                    #pragma unroll
                    for (int r = 0; r < 4; r++)
                        *(float4*)av[r] = *(const float4*)(As + (row0 + r) * PTCH + k4 * 4);
                    #pragma unroll
                    for (int kk = 0; kk < 4; kk++) {
                        const int k = k4 * 4 + kk;
                        float bv[8];
                        *(float4*)&bv[0] = *(const float4*)(As + k * PTCH + col0);
                        *(float4*)&bv[4] = *(const float4*)(As + k * PTCH + col0 + 4);
                        #pragma unroll
                        for (int r = 0; r < 4; r++)
                            #pragma unroll
                            for (int e = 0; e < 8; e++)
                                t[r][e] += av[r][kk] * bv[e];
                    }
                }
            }
            __syncthreads();
            if (act) {
                #pragma unroll
                for (int r = 0; r < 4; r++) {
                    *(float4*)(As + (row0 + r) * PTCH + col0)     = *(float4*)&t[r][0];
                    *(float4*)(As + (row0 + r) * PTCH + col0 + 4) = *(float4*)&t[r][4];
                }
            }
            __syncthreads();
        }
    }
    for (int idx = tid; idx < RB * RB; idx += 512) {
        const int i = idx >> 6, j = idx & 63;
        g_MT[(size_t)blk * RB * RB + idx] = Bs[j * PTCH + i];
    }
}

// ---------------- scan phase B1: chain (sequential, 1 CTA/batch) -----------------
__global__ __launch_bounds__(1024, 1) void scan_chain(
    const float* __restrict__ xi, const float* __restrict__ sz,
    __half* __restrict__ gf)
{
    __shared__ float h0s[DI];
    __shared__ float MTs[RB * RB];
    __shared__ float fs[RB];
    __shared__ float as[RB];

    const int b = blockIdx.x;
    const int tid = threadIdx.x;
    const int lane = tid & 31, wrp = tid >> 5;
    const int c0 = tid * 2;

    const float* xib = xi + (size_t)b * TT * DI;
    const float* szb = sz + (size_t)b * TT * DI;
    __half* gfb = gf + (size_t)b * TT * DI;

    float2 h0 = *(const float2*)(xib + c0);
    {
        const float2 s0 = *(const float2*)(szb + c0);
        __half2 p = __floats2half2_rn(s0.x * h0.x, s0.y * h0.y);
        *(uint32_t*)(gfb + c0) = *(uint32_t*)&p;
        *(float2*)(h0s + c0) = h0;
    }
    __syncthreads();

    for (int n = 0; n < NBLK; n++) {
        const int blk = b * 32 + n;
        const int J = (n == 31) ? 63 : 64;
        const size_t base = (size_t)blk * RB * DI;

        for (int idx = tid; idx < RB * RB; idx += 1024)
            MTs[idx] = g_MT[(size_t)blk * RB * RB + idx];

        for (int r = wrp; r < RB; r += 32) {
            float s = 0.f;
            if (r < J) {
                const float4* a4p = (const float4*)(g_Vt + base + (size_t)r * DI);
                #pragma unroll
                for (int i = 0; i < 16; i++) {
                    const int ci = lane + i * 32;
                    const float4 a4 = a4p[ci];
                    const float4 h4 = *(const float4*)(h0s + ci * 4);
                    s += a4.x * h4.x + a4.y * h4.y + a4.z * h4.z + a4.w * h4.w;
                }
                #pragma unroll
                for (int o = 16; o; o >>= 1) s += __shfl_xor_sync(~0u, s, o);
            }
            if (lane == 0) fs[r] = s + g_crow[blk * RB + r];
        }
        __syncthreads();

        if (tid < RB) {
            float s = 0.f;
            #pragma unroll 8
            for (int i = 0; i < RB; i++)
                s += MTs[i * RB + tid] * fs[i];
            as[tid] = s;
            g_as[blk * RB + tid] = s;
        }
        __syncthreads();

        *(float2*)(g_h0e + (size_t)blk * DI + c0) = h0;

        float2 ws = make_float2(0.f, 0.f);
        #pragma unroll 8
        for (int j = 0; j < RB; j++) {
            const float2 wh = *(const float2*)(g_Wh + base + (size_t)j * DI + c0);
            const float aj = as[j];
            ws.x += wh.x * aj; ws.y += wh.y * aj;
        }
        const float2 la = *(const float2*)(g_Lam  + base + (size_t)(J - 1) * DI + c0);
        const float2 cu = *(const float2*)(g_CumU + base + (size_t)(J - 1) * DI + c0);
        h0.x = la.x * (h0.x + cu.x - ws.x);
        h0.y = la.y * (h0.y + cu.y - ws.y);
        *(float2*)(h0s + c0) = h0;
        __syncthreads();
    }
}

// ---------------- scan phase B2: reconstruction (parallel over 128 blocks) -------
__global__ __launch_bounds__(512, 1) void scan_recon(
    const float* __restrict__ sz, __half* __restrict__ gf)
{
    __shared__ float as[RB];
    const int blk = blockIdx.x;
    const int b = blk >> 5, n = blk & 31;
    const int t0 = n * 64 + 1;
    const int J = (n == 31) ? 63 : 64;
    const int tid = threadIdx.x;
    const int c0 = tid * 4;
    const size_t base = (size_t)blk * RB * DI;

    if (tid < RB) as[tid] = g_as[blk * RB + tid];
    __syncthreads();

    const float* szb = sz + (size_t)b * TT * DI;
    __half* gfb = gf + (size_t)b * TT * DI;

    const float4 h0 = *(const float4*)(g_h0e + (size_t)blk * DI + c0);
    float4 ws = make_float4(0.f, 0.f, 0.f, 0.f);

    for (int j = 0; j < J; j++) {
        const size_t o = base + (size_t)j * DI + c0;
        const float4 wh = *(const float4*)(g_Wh + o);
        const float4 cu = *(const float4*)(g_CumU + o);
        const float4 la = *(const float4*)(g_Lam + o);
        const float4 s4 = *(const float4*)(szb + (size_t)(t0 + j) * DI + c0);
        const float aj = as[j];
        ws.x += wh.x * aj; ws.y += wh.y * aj;
        ws.z += wh.z * aj; ws.w += wh.w * aj;
        float4 hj;
        hj.x = la.x * (h0.x + cu.x - ws.x);
        hj.y = la.y * (h0.y + cu.y - ws.y);
        hj.z = la.z * (h0.z + cu.z - ws.z);
        hj.w = la.w * (h0.w + cu.w - ws.w);
        __half2 p0 = __floats2half2_rn(s4.x * hj.x, s4.y * hj.y);
        __half2 p1 = __floats2half2_rn(s4.z * hj.z, s4.w * hj.w);
        *(uint2*)(gfb + (size_t)(t0 + j) * DI + c0) =
            make_uint2(*(uint32_t*)&p0, *(uint32_t*)&p1);
    }
}

// ---------------- launcher ----------------------------------------------------------
extern "C" void kernel_launch(void* const* d_in, const int* in_sizes, int n_in,
                              void* d_out, int out_size)
{
    const float* x     = (const float*)d_in[0];
    const float* omega = (const float*)d_in[1];
    const float* Win   = (const float*)d_in[2];
    const float* Wl    = (const float*)d_in[3];
    const float* bl    = (const float*)d_in[4];
    const float* Wv    = (const float*)d_in[5];
    const float* bv    = (const float*)d_in[6];
    const float* Wout  = (const float*)d_in[7];
    float* out = (float*)d_out;

    __nv_bfloat16 *xh, *xl, *winh, *winl, *wvh, *wvl, *xih, *xil;
    __half *xf, *wzf, *wlf, *wof, *xif, *gfp;
    float *xi, *szp, *lam, *v, *fcol;
    cudaGetSymbolAddress((void**)&xh,   g_xh);   cudaGetSymbolAddress((void**)&xl,   g_xl);
    cudaGetSymbolAddress((void**)&xf,   g_xf);
    cudaGetSymbolAddress((void**)&winh, g_winh); cudaGetSymbolAddress((void**)&winl, g_winl);
    cudaGetSymbolAddress((void**)&wzf,  g_wzf);  cudaGetSymbolAddress((void**)&wlf,  g_wlf);
    cudaGetSymbolAddress((void**)&wvh,  g_wvh);  cudaGetSymbolAddress((void**)&wvl,  g_wvl);
    cudaGetSymbolAddress((void**)&wof,  g_wof);
    cudaGetSymbolAddress((void**)&xi,   g_xi);
    cudaGetSymbolAddress((void**)&xih,  g_xih);  cudaGetSymbolAddress((void**)&xil,  g_xil);
    cudaGetSymbolAddress((void**)&xif,  g_xif);
    cudaGetSymbolAddress((void**)&szp,  g_sz);
    cudaGetSymbolAddress((void**)&lam,  g_lam);  cudaGetSymbolAddress((void**)&v,    g_v);
    cudaGetSymbolAddress((void**)&gfp,  g_gf);
    cudaGetSymbolAddress((void**)&fcol, g_fcolA);

    cudaFuncSetAttribute(gemm_ps, cudaFuncAttributeMaxDynamicSharedMemorySize, GEMM_SMEM);
    cudaFuncSetAttribute(gemm_f16, cudaFuncAttributeMaxDynamicSharedMemorySize, F16_SMEM);
    cudaFuncSetAttribute(scan_prep, cudaFuncAttributeMaxDynamicSharedMemorySize, SMEMA);

    // 0) splits + fp16 casts (7 segs)
    mega_pre<<<dim3((MROWS * DM) / 1024, 7), 256>>>(x, Win, Wl, Wv, Wout);

    // 1) fcol
    fcol_kernel<<<DI / 256, 256>>>(omega, fcol);

    // 2) GEMM1-xi: xi = x @ Win[0:DI)^T  [3-term bf16] -> fp32 + split + fp16
    gemm_ps<<<dim3(DI / 128, MROWS / 128), GT, GEMM_SMEM>>>(
        xh, xl, DM, winh, winl, DM, DM,
        xi, DI, nullptr, xih, xil, xif, 2);

    // 3) fused fp16: z=0 -> sz = silu(x @ Winz^T), z=1 -> lam epi   (ncu idx 3)
    gemm_f16<<<dim3(DI / 128, MROWS / 128, 2), GT, F16_SMEM>>>(
        xf, DM, wzf, DM, DM,
        xif, DI, wlf, DI, DI,
        szp, DI, lam, DI,
        nullptr, bl, fcol, 3, 1);

    // 4) GEMM-v: v = xi @ Wv^T + bv  [3-term bf16]
    gemm_ps<<<dim3(DI / 128, MROWS / 128), GT, GEMM_SMEM>>>(
        xih, xil, DI, wvh, wvl, DI, DI,
        v, DI, bv, nullptr, nullptr, nullptr, 0);

    // 5) scan prep
    scan_prep<<<TOTBLK, 512, SMEMA>>>(xi, lam, v);

    // 6) chain
    scan_chain<<<BB, 1024>>>(xi, szp, gfp);

    // 7) reconstruction
    scan_recon<<<TOTBLK, 512>>>(szp, gfp);

    // 8) GEMM4: out = g @ Wout^T  [fp16]
    gemm_f16<<<dim3(DM / 128, MROWS / 128, 1), GT, F16_SMEM>>>(
        gfp, DI, wof, DI, DI,
        nullptr, 0, nullptr, 0, 0,
        out, DM, nullptr, 0,
        nullptr, nullptr, fcol, 0, 0);
}